// round 2
// baseline (speedup 1.0000x reference)
#include <cuda_runtime.h>

#define BATCH 4
#define SEQ   4096
#define HID   256
#define MTOT  (BATCH * SEQ)

// Scratch for projected Q, K, V (16 MB each). Q is pre-scaled by 1/sqrt(H) at
// attention load time instead (cheaper: folded into smem fill).
__device__ float g_Q[MTOT * HID];
__device__ float g_K[MTOT * HID];
__device__ float g_V[MTOT * HID];

// ---------------------------------------------------------------------------
// Kernel 1: fused QKV projection.
// Out[m][n] = sum_k X[m][k] * W[k][n];  M=16384, N=256, K=256.
// blockIdx.z selects {Q, K, V}. BM=64, BN=64, BK=32, 256 threads, 4x4/thread.
// ---------------------------------------------------------------------------
__global__ __launch_bounds__(256) void qkv_gemm(
    const float* __restrict__ X,
    const float* __restrict__ Wq,
    const float* __restrict__ Wk,
    const float* __restrict__ Wv)
{
    __shared__ float As[64][33];   // padded: broadcast-friendly reads
    __shared__ float Bs[32][64];

    const float* W;
    float* O;
    if (blockIdx.z == 0)      { W = Wq; O = g_Q; }
    else if (blockIdx.z == 1) { W = Wk; O = g_K; }
    else                      { W = Wv; O = g_V; }

    const int bm = blockIdx.x * 64;
    const int bn = blockIdx.y * 64;
    const int t  = threadIdx.x;
    const int tx = t & 15;
    const int ty = t >> 4;

    float acc[4][4] = {};

    for (int k0 = 0; k0 < HID; k0 += 32) {
        // Load A tile 64x32 (512 float4, 2 per thread), coalesced.
        #pragma unroll
        for (int e = 0; e < 2; e++) {
            int f  = e * 256 + t;
            int m  = f >> 3;
            int k4 = f & 7;
            float4 v = *reinterpret_cast<const float4*>(X + (size_t)(bm + m) * HID + k0 + k4 * 4);
            As[m][k4 * 4 + 0] = v.x;
            As[m][k4 * 4 + 1] = v.y;
            As[m][k4 * 4 + 2] = v.z;
            As[m][k4 * 4 + 3] = v.w;
        }
        // Load B tile 32x64 (512 float4, 2 per thread), coalesced.
        #pragma unroll
        for (int e = 0; e < 2; e++) {
            int f  = e * 256 + t;
            int k  = f >> 4;
            int n4 = f & 15;
            float4 v = *reinterpret_cast<const float4*>(W + (size_t)(k0 + k) * HID + bn + n4 * 4);
            *reinterpret_cast<float4*>(&Bs[k][n4 * 4]) = v;
        }
        __syncthreads();

        #pragma unroll
        for (int kk = 0; kk < 32; kk++) {
            float a0 = As[ty * 4 + 0][kk];
            float a1 = As[ty * 4 + 1][kk];
            float a2 = As[ty * 4 + 2][kk];
            float a3 = As[ty * 4 + 3][kk];
            float4 bb = *reinterpret_cast<const float4*>(&Bs[kk][tx * 4]);
            acc[0][0] += a0 * bb.x; acc[0][1] += a0 * bb.y; acc[0][2] += a0 * bb.z; acc[0][3] += a0 * bb.w;
            acc[1][0] += a1 * bb.x; acc[1][1] += a1 * bb.y; acc[1][2] += a1 * bb.z; acc[1][3] += a1 * bb.w;
            acc[2][0] += a2 * bb.x; acc[2][1] += a2 * bb.y; acc[2][2] += a2 * bb.z; acc[2][3] += a2 * bb.w;
            acc[3][0] += a3 * bb.x; acc[3][1] += a3 * bb.y; acc[3][2] += a3 * bb.z; acc[3][3] += a3 * bb.w;
        }
        __syncthreads();
    }

    #pragma unroll
    for (int r = 0; r < 4; r++) {
        float4 v;
        v.x = acc[r][0]; v.y = acc[r][1]; v.z = acc[r][2]; v.w = acc[r][3];
        *reinterpret_cast<float4*>(O + (size_t)(bm + ty * 4 + r) * HID + bn + tx * 4) = v;
    }
}

// ---------------------------------------------------------------------------
// Kernel 2: flash-attention (fp32, online softmax).
// One CTA per (batch, 64-query tile). 256 threads.
// Thread t: row i = t&63, column-group jc = t>>6 (16 score cols / 64 out dims).
// ---------------------------------------------------------------------------
#define QS_STRIDE 260                 // 256 + 4 pad (keeps 16B alignment)
#define PS_STRIDE 65                  // odd stride -> conflict-free row reads
#define SMEM_F (64 * QS_STRIDE + 2 * 64 * 256 + 64 * PS_STRIDE + 2 * 256)
#define SMEM_BYTES (SMEM_F * 4)

__global__ __launch_bounds__(256, 1) void attn(float* __restrict__ out)
{
    extern __shared__ float sm[];
    float* Qs = sm;                          // 64 x QS_STRIDE (pre-scaled Q)
    float* Ks = Qs + 64 * QS_STRIDE;         // 64 x 256
    float* Vs = Ks + 64 * 256;               // 64 x 256
    float* Ps = Vs + 64 * 256;               // 64 x PS_STRIDE
    float* Rm = Ps + 64 * PS_STRIDE;         // 64 x 4 (rowmax partials)
    float* Rs = Rm + 256;                    // 64 x 4 (rowsum partials)

    const int b  = blockIdx.y;
    const int q0 = blockIdx.x * 64;
    const int t  = threadIdx.x;
    const float scale = 0.0625f;             // 1/sqrt(256)

    // Load + scale Q tile (64x256), coalesced float4.
    const float* Qg = g_Q + ((size_t)b * SEQ + q0) * HID;
    #pragma unroll
    for (int e = 0; e < 16; e++) {
        int f  = e * 256 + t;
        int i  = f >> 6;
        int d4 = f & 63;
        float4 v = *reinterpret_cast<const float4*>(Qg + (size_t)i * HID + d4 * 4);
        v.x *= scale; v.y *= scale; v.z *= scale; v.w *= scale;
        *reinterpret_cast<float4*>(Qs + i * QS_STRIDE + d4 * 4) = v;
    }

    const int i  = t & 63;     // my query row within tile
    const int jc = t >> 6;     // 0..3
    const int cb = jc * 64;    // my output-dim chunk base

    float m_old = -1e30f;
    float l = 0.0f;
    float4 O4[16];
    #pragma unroll
    for (int e = 0; e < 16; e++) O4[e] = make_float4(0.f, 0.f, 0.f, 0.f);

    const float* Kg = g_K + (size_t)b * SEQ * HID;
    const float* Vg = g_V + (size_t)b * SEQ * HID;

    for (int kt = 0; kt < SEQ / 64; kt++) {
        __syncthreads();   // previous iteration's Vs/Ps reads done
        const float* Ktile = Kg + (size_t)kt * 64 * HID;
        const float* Vtile = Vg + (size_t)kt * 64 * HID;
        #pragma unroll
        for (int e = 0; e < 16; e++) {
            int f  = e * 256 + t;
            int r  = f >> 6;
            int d4 = f & 63;
            *reinterpret_cast<float4*>(Ks + r * 256 + d4 * 4) =
                *reinterpret_cast<const float4*>(Ktile + (size_t)r * HID + d4 * 4);
            *reinterpret_cast<float4*>(Vs + r * 256 + d4 * 4) =
                *reinterpret_cast<const float4*>(Vtile + (size_t)r * HID + d4 * 4);
        }
        __syncthreads();

        // S[i][jc*16+jj] = Qs[i] . Ks[j]   (Q pre-scaled)
        float s[16];
        #pragma unroll
        for (int jj = 0; jj < 16; jj++) s[jj] = 0.f;

        const float4* Qr = reinterpret_cast<const float4*>(Qs + i * QS_STRIDE);
        for (int d4 = 0; d4 < 64; d4++) {
            float4 a = Qr[d4];
            #pragma unroll
            for (int jj = 0; jj < 16; jj++) {
                float4 bv = *reinterpret_cast<const float4*>(Ks + (jc * 16 + jj) * 256 + d4 * 4);
                s[jj] += a.x * bv.x + a.y * bv.y + a.z * bv.z + a.w * bv.w;
            }
        }

        // Online softmax: row max across 4 thread-groups
        float lm = s[0];
        #pragma unroll
        for (int jj = 1; jj < 16; jj++) lm = fmaxf(lm, s[jj]);
        Rm[i * 4 + jc] = lm;
        __syncthreads();
        float rmax = fmaxf(fmaxf(Rm[i * 4 + 0], Rm[i * 4 + 1]),
                           fmaxf(Rm[i * 4 + 2], Rm[i * 4 + 3]));
        float m_new = fmaxf(m_old, rmax);
        float alpha = __expf(m_old - m_new);

        float ls = 0.f;
        #pragma unroll
        for (int jj = 0; jj < 16; jj++) {
            float p = __expf(s[jj] - m_new);
            ls += p;
            Ps[i * PS_STRIDE + jc * 16 + jj] = p;
        }
        Rs[i * 4 + jc] = ls;
        __syncthreads();
        l = l * alpha + (Rs[i * 4 + 0] + Rs[i * 4 + 1] + Rs[i * 4 + 2] + Rs[i * 4 + 3]);
        m_old = m_new;

        // Rescale accumulator, then O += P . V
        #pragma unroll
        for (int e = 0; e < 16; e++) {
            O4[e].x *= alpha; O4[e].y *= alpha; O4[e].z *= alpha; O4[e].w *= alpha;
        }
        for (int j = 0; j < 64; j++) {
            float p = Ps[i * PS_STRIDE + j];
            const float4* Vr = reinterpret_cast<const float4*>(Vs + j * 256 + cb);
            #pragma unroll
            for (int e = 0; e < 16; e++) {
                float4 v = Vr[e];
                O4[e].x += p * v.x; O4[e].y += p * v.y;
                O4[e].z += p * v.z; O4[e].w += p * v.w;
            }
        }
    }

    // Normalize and write out[b][q0+i][cb..cb+63]
    float inv = 1.0f / l;
    float* og = out + (((size_t)b * SEQ) + q0 + i) * HID + cb;
    #pragma unroll
    for (int e = 0; e < 16; e++) {
        float4 v = O4[e];
        v.x *= inv; v.y *= inv; v.z *= inv; v.w *= inv;
        *reinterpret_cast<float4*>(og + e * 4) = v;
    }
}

// ---------------------------------------------------------------------------
extern "C" void kernel_launch(void* const* d_in, const int* in_sizes, int n_in,
                              void* d_out, int out_size)
{
    const float* X  = (const float*)d_in[0];
    const float* Wq = (const float*)d_in[1];
    const float* Wk = (const float*)d_in[2];
    const float* Wv = (const float*)d_in[3];
    // d_in[4] = lengths (int64) — unused by the reference module.
    float* out = (float*)d_out;

    cudaFuncSetAttribute(attn, cudaFuncAttributeMaxDynamicSharedMemorySize, SMEM_BYTES);

    qkv_gemm<<<dim3(MTOT / 64, HID / 64, 3), 256>>>(X, Wq, Wk, Wv);
    attn<<<dim3(SEQ / 64, BATCH), 256, SMEM_BYTES>>>(out);
}

// round 7
// speedup vs baseline: 1.7291x; 1.7291x over previous
#include <cuda_runtime.h>
#include <cuda_bf16.h>
#include <mma.h>
#include <cstdint>
using namespace nvcuda;

#define BATCH 4
#define SEQ   4096
#define HID   256
#define MTOT  (BATCH * SEQ)

__device__ __align__(16) __nv_bfloat16 g_Qh[MTOT * HID];
__device__ __align__(16) __nv_bfloat16 g_Ql[MTOT * HID];
__device__ __align__(16) __nv_bfloat16 g_Kh[MTOT * HID];
__device__ __align__(16) __nv_bfloat16 g_Kl[MTOT * HID];
__device__ __align__(16) float         g_V [MTOT * HID];

__device__ __forceinline__ float tf32r(float x) {
    float y; asm("cvt.rna.tf32.f32 %0, %1;" : "=f"(y) : "f"(x)); return y;
}
__device__ __forceinline__ uint32_t smem_u32(const void* p) {
    uint32_t a;
    asm("{ .reg .u64 t; cvta.to.shared.u64 t, %1; cvt.u32.u64 %0, t; }" : "=r"(a) : "l"(p));
    return a;
}
#define CPA(dst, src) \
    asm volatile("cp.async.cg.shared.global [%0], [%1], 16;" :: "r"(dst), "l"(src))
#define CP_COMMIT() asm volatile("cp.async.commit_group;" ::: "memory")
#define CP_WAIT(n)  asm volatile("cp.async.wait_group %0;" :: "n"(n) : "memory")

// ---------------------------------------------------------------------------
// Kernel 1: fused QKV projection (fp32 GEMM), outputs split/rounded operands.
// ---------------------------------------------------------------------------
__global__ __launch_bounds__(256) void qkv_gemm(
    const float* __restrict__ X, const float* __restrict__ Wq,
    const float* __restrict__ Wk, const float* __restrict__ Wv)
{
    __shared__ float As[64][33];
    __shared__ float Bs[32][64];
    const int z = blockIdx.z;
    const float* W = (z == 0) ? Wq : (z == 1) ? Wk : Wv;
    const int bm = blockIdx.x * 64, bn = blockIdx.y * 64;
    const int t = threadIdx.x, tx = t & 15, ty = t >> 4;
    float acc[4][4] = {};

    for (int k0 = 0; k0 < HID; k0 += 32) {
        #pragma unroll
        for (int e = 0; e < 2; e++) {
            int f = e * 256 + t, m = f >> 3, k4 = f & 7;
            float4 v = *reinterpret_cast<const float4*>(X + (size_t)(bm + m) * HID + k0 + k4 * 4);
            As[m][k4 * 4 + 0] = v.x; As[m][k4 * 4 + 1] = v.y;
            As[m][k4 * 4 + 2] = v.z; As[m][k4 * 4 + 3] = v.w;
        }
        #pragma unroll
        for (int e = 0; e < 2; e++) {
            int f = e * 256 + t, k = f >> 4, n4 = f & 15;
            float4 v = *reinterpret_cast<const float4*>(W + (size_t)(k0 + k) * HID + bn + n4 * 4);
            *reinterpret_cast<float4*>(&Bs[k][n4 * 4]) = v;
        }
        __syncthreads();
        #pragma unroll
        for (int kk = 0; kk < 32; kk++) {
            float a0 = As[ty * 4 + 0][kk], a1 = As[ty * 4 + 1][kk];
            float a2 = As[ty * 4 + 2][kk], a3 = As[ty * 4 + 3][kk];
            float4 bb = *reinterpret_cast<const float4*>(&Bs[kk][tx * 4]);
            acc[0][0] += a0 * bb.x; acc[0][1] += a0 * bb.y; acc[0][2] += a0 * bb.z; acc[0][3] += a0 * bb.w;
            acc[1][0] += a1 * bb.x; acc[1][1] += a1 * bb.y; acc[1][2] += a1 * bb.z; acc[1][3] += a1 * bb.w;
            acc[2][0] += a2 * bb.x; acc[2][1] += a2 * bb.y; acc[2][2] += a2 * bb.z; acc[2][3] += a2 * bb.w;
            acc[3][0] += a3 * bb.x; acc[3][1] += a3 * bb.y; acc[3][2] += a3 * bb.z; acc[3][3] += a3 * bb.w;
        }
        __syncthreads();
    }

    if (z == 2) {
        #pragma unroll
        for (int r = 0; r < 4; r++) {
            size_t base = (size_t)(bm + ty * 4 + r) * HID + bn + tx * 4;
            #pragma unroll
            for (int c = 0; c < 4; c++) g_V[base + c] = tf32r(acc[r][c]);
        }
    } else {
        const float s = (z == 0) ? 0.0625f : 1.0f;       // fold 1/sqrt(256) into Q
        __nv_bfloat16* Gh = (z == 0) ? g_Qh : g_Kh;
        __nv_bfloat16* Gl = (z == 0) ? g_Ql : g_Kl;
        #pragma unroll
        for (int r = 0; r < 4; r++) {
            size_t base = (size_t)(bm + ty * 4 + r) * HID + bn + tx * 4;
            #pragma unroll
            for (int c = 0; c < 4; c++) {
                float v = acc[r][c] * s;
                __nv_bfloat16 h = __float2bfloat16_rn(v);
                Gh[base + c] = h;
                Gl[base + c] = __float2bfloat16_rn(v - __bfloat162float(h));
            }
        }
    }
}

// ---------------------------------------------------------------------------
// Kernel 2: wmma flash attention, two-pass fixed row max.
// 64 q rows / CTA, 32-key tiles, 256 threads / 8 warps.
// ---------------------------------------------------------------------------
#define KT 32
#define NT (SEQ / KT)     // 128 tiles
#define LDQ 272           // bf16 elems (544 B/row)
#define LDK 272
#define LDV 264           // f32 elems (1056 B/row)
#define LDP 36            // f32 elems
#define LDO 264

#define OFF_QH  0
#define OFF_QL  34816
#define OFF_BUF 69632
#define BUF_SZ  68608
#define BKH 0
#define BKL 17408
#define BV  34816
#define OFF_S  206848
#define OFF_RM 216064
#define OFF_RL 217088
#define SMEM_TOTAL 218112

__global__ __launch_bounds__(256, 1) void attn(float* __restrict__ out)
{
    extern __shared__ __align__(1024) char smem[];
    const uint32_t sm32 = smem_u32(smem);
    const int tid = threadIdx.x;
    const int w = tid >> 5;
    const int mw = w & 3, dw = w >> 2;
    const int r = tid >> 2, g = tid & 3;     // softmax row / col-group

    const int b  = blockIdx.y;
    const int q0 = blockIdx.x * 64;

    const char* QhG = (const char*)(g_Qh + (size_t)(b * SEQ + q0) * HID);
    const char* QlG = (const char*)(g_Ql + (size_t)(b * SEQ + q0) * HID);
    const char* KhG = (const char*)(g_Kh + (size_t)b * SEQ * HID);
    const char* KlG = (const char*)(g_Kl + (size_t)b * SEQ * HID);
    const char* VG  = (const char*)(g_V  + (size_t)b * SEQ * HID);

    // Q load (once): 64 rows x 512 B each matrix
    #pragma unroll
    for (int e = 0; e < 8; e++) {
        int c = e * 256 + tid, row = c >> 5, col = c & 31;
        CPA(sm32 + OFF_QH + row * 544 + col * 16, QhG + (size_t)row * 512 + col * 16);
        CPA(sm32 + OFF_QL + row * 544 + col * 16, QlG + (size_t)row * 512 + col * 16);
    }

    auto loadK1 = [&](int kt) {
        uint32_t base = sm32 + OFF_BUF + (kt & 1) * BUF_SZ;
        const char* src = KhG + (size_t)kt * KT * 512;
        #pragma unroll
        for (int e = 0; e < 4; e++) {
            int c = e * 256 + tid, row = c >> 5, col = c & 31;
            CPA(base + BKH + row * 544 + col * 16, src + (size_t)row * 512 + col * 16);
        }
    };
    auto loadKV = [&](int kt) {
        loadK1(kt);
        uint32_t base = sm32 + OFF_BUF + (kt & 1) * BUF_SZ;
        const char* sl = KlG + (size_t)kt * KT * 512;
        #pragma unroll
        for (int e = 0; e < 4; e++) {
            int c = e * 256 + tid, row = c >> 5, col = c & 31;
            CPA(base + BKL + row * 544 + col * 16, sl + (size_t)row * 512 + col * 16);
        }
        const char* sv = VG + (size_t)kt * KT * 1024;
        #pragma unroll
        for (int e = 0; e < 8; e++) {
            int c = e * 256 + tid, row = c >> 6, col = c & 63;
            CPA(base + BV + row * 1056 + col * 16, sv + (size_t)row * 1024 + col * 16);
        }
    };

    const __nv_bfloat16* Qhs = (const __nv_bfloat16*)(smem + OFF_QH);
    const __nv_bfloat16* Qls = (const __nv_bfloat16*)(smem + OFF_QL);
    float* Ps = (float*)(smem + OFF_S);
    float* Rm = (float*)(smem + OFF_RM);
    float* Rl = (float*)(smem + OFF_RL);

    // ================= Pass 1: row max (hi-only QK) =================
    loadK1(0);
    CP_COMMIT();
    float mpart = -1e30f;
    for (int kt = 0; kt < NT; kt++) {
        __syncthreads();
        if (kt + 1 < NT) { loadK1(kt + 1); CP_COMMIT(); CP_WAIT(1); }
        else             { CP_WAIT(0); }
        __syncthreads();
        const __nv_bfloat16* Khs =
            (const __nv_bfloat16*)(smem + OFF_BUF + (kt & 1) * BUF_SZ + BKH);
        wmma::fragment<wmma::matrix_a, 16, 16, 16, __nv_bfloat16, wmma::row_major> ah;
        wmma::fragment<wmma::matrix_b, 16, 16, 16, __nv_bfloat16, wmma::col_major> bh;
        wmma::fragment<wmma::accumulator, 16, 16, 16, float> sacc;
        wmma::fill_fragment(sacc, 0.0f);
        #pragma unroll
        for (int kk = 0; kk < 16; kk++) {
            wmma::load_matrix_sync(ah, Qhs + mw * 16 * LDQ + kk * 16, LDQ);
            wmma::load_matrix_sync(bh, Khs + dw * 16 * LDK + kk * 16, LDK);
            wmma::mma_sync(sacc, ah, bh, sacc);
        }
        wmma::store_matrix_sync(Ps + mw * 16 * LDP + dw * 16, sacc, LDP, wmma::mem_row_major);
        __syncthreads();
        const float* prow = Ps + r * LDP + g * 8;
        #pragma unroll
        for (int j = 0; j < 8; j++) mpart = fmaxf(mpart, prow[j]);
    }
    Rm[r * 4 + g] = mpart;
    __syncthreads();
    const float mrow = fmaxf(fmaxf(Rm[r * 4 + 0], Rm[r * 4 + 1]),
                             fmaxf(Rm[r * 4 + 2], Rm[r * 4 + 3]));

    // ================= Pass 2: softmax + PV =================
    wmma::fragment<wmma::accumulator, 16, 16, 8, float> accO[8];
    #pragma unroll
    for (int n = 0; n < 8; n++) wmma::fill_fragment(accO[n], 0.0f);
    float lpart = 0.0f;

    __syncthreads();
    loadKV(0);
    CP_COMMIT();
    for (int kt = 0; kt < NT; kt++) {
        __syncthreads();
        if (kt + 1 < NT) { loadKV(kt + 1); CP_COMMIT(); CP_WAIT(1); }
        else             { CP_WAIT(0); }
        __syncthreads();
        const char* buf = smem + OFF_BUF + (kt & 1) * BUF_SZ;
        const __nv_bfloat16* Khs = (const __nv_bfloat16*)(buf + BKH);
        const __nv_bfloat16* Kls = (const __nv_bfloat16*)(buf + BKL);
        const float*         Vs  = (const float*)(buf + BV);

        {   // QK^T bf16 x3
            wmma::fragment<wmma::matrix_a, 16, 16, 16, __nv_bfloat16, wmma::row_major> ah, al;
            wmma::fragment<wmma::matrix_b, 16, 16, 16, __nv_bfloat16, wmma::col_major> bh, bl;
            wmma::fragment<wmma::accumulator, 16, 16, 16, float> sacc;
            wmma::fill_fragment(sacc, 0.0f);
            #pragma unroll
            for (int kk = 0; kk < 16; kk++) {
                wmma::load_matrix_sync(ah, Qhs + mw * 16 * LDQ + kk * 16, LDQ);
                wmma::load_matrix_sync(al, Qls + mw * 16 * LDQ + kk * 16, LDQ);
                wmma::load_matrix_sync(bh, Khs + dw * 16 * LDK + kk * 16, LDK);
                wmma::load_matrix_sync(bl, Kls + dw * 16 * LDK + kk * 16, LDK);
                wmma::mma_sync(sacc, ah, bh, sacc);
                wmma::mma_sync(sacc, ah, bl, sacc);
                wmma::mma_sync(sacc, al, bh, sacc);
            }
            wmma::store_matrix_sync(Ps + mw * 16 * LDP + dw * 16, sacc, LDP, wmma::mem_row_major);
        }
        __syncthreads();

        {   // softmax with fixed row max
            float* prow = Ps + r * LDP + g * 8;
            #pragma unroll
            for (int j = 0; j < 8; j++) {
                float p = tf32r(__expf(prow[j] - mrow));
                lpart += p;
                prow[j] = p;
            }
        }
        __syncthreads();

        {   // PV: accO += P(64xKT) * V(KTx256), tf32
            wmma::fragment<wmma::matrix_a, 16, 16, 8, wmma::precision::tf32, wmma::row_major> pa;
            wmma::fragment<wmma::matrix_b, 16, 16, 8, wmma::precision::tf32, wmma::row_major> vb;
            #pragma unroll
            for (int k = 0; k < KT / 8; k++) {
                wmma::load_matrix_sync(pa, Ps + mw * 16 * LDP + k * 8, LDP);
                #pragma unroll
                for (int n = 0; n < 8; n++) {
                    wmma::load_matrix_sync(vb, Vs + (k * 8) * LDV + dw * 128 + n * 16, LDV);
                    wmma::mma_sync(accO[n], pa, vb, accO[n]);
                }
            }
        }
    }

    // ================= Epilogue =================
    float* Os = (float*)(smem + OFF_BUF);    // staging (buf0 area, no longer read)
    #pragma unroll
    for (int n = 0; n < 8; n++)
        wmma::store_matrix_sync(Os + mw * 16 * LDO + dw * 128 + n * 16, accO[n],
                                LDO, wmma::mem_row_major);
    Rl[r * 4 + g] = lpart;
    __syncthreads();
    const float linv = 1.0f / (Rl[r * 4 + 0] + Rl[r * 4 + 1] + Rl[r * 4 + 2] + Rl[r * 4 + 3]);
    float* orow = out + (size_t)(b * SEQ + q0 + r) * HID + g * 64;
    const float* srow = Os + r * LDO + g * 64;
    #pragma unroll
    for (int j = 0; j < 16; j++) {
        float4 v = *reinterpret_cast<const float4*>(srow + j * 4);
        v.x *= linv; v.y *= linv; v.z *= linv; v.w *= linv;
        *reinterpret_cast<float4*>(orow + j * 4) = v;
    }
}

// ---------------------------------------------------------------------------
extern "C" void kernel_launch(void* const* d_in, const int* in_sizes, int n_in,
                              void* d_out, int out_size)
{
    const float* X  = (const float*)d_in[0];
    const float* Wq = (const float*)d_in[1];
    const float* Wk = (const float*)d_in[2];
    const float* Wv = (const float*)d_in[3];
    // d_in[4] = lengths (unused by the reference module)
    float* out = (float*)d_out;

    cudaFuncSetAttribute(attn, cudaFuncAttributeMaxDynamicSharedMemorySize, SMEM_TOTAL);

    qkv_gemm<<<dim3(MTOT / 64, HID / 64, 3), 256>>>(X, Wq, Wk, Wv);
    attn<<<dim3(SEQ / 64, BATCH), 256, SMEM_TOTAL>>>(out);
}

// round 8
// speedup vs baseline: 2.5109x; 1.4521x over previous
#include <cuda_runtime.h>
#include <cuda_bf16.h>
#include <mma.h>
#include <cstdint>
using namespace nvcuda;

#define BATCH 4
#define SEQ   4096
#define HID   256
#define MTOT  (BATCH * SEQ)

__device__ __align__(16) __nv_bfloat16 g_Qh[MTOT * HID];
__device__ __align__(16) __nv_bfloat16 g_Ql[MTOT * HID];
__device__ __align__(16) __nv_bfloat16 g_Kh[MTOT * HID];
__device__ __align__(16) __nv_bfloat16 g_Kl[MTOT * HID];
__device__ __align__(16) float         g_V [MTOT * HID];
__device__ __align__(16) float         g_S [(size_t)BATCH * SEQ * SEQ];   // 256 MB scratch
__device__ unsigned g_rmax[MTOT];

__device__ __forceinline__ float tf32r(float x) {
    float y; asm("cvt.rna.tf32.f32 %0, %1;" : "=f"(y) : "f"(x)); return y;
}
__device__ __forceinline__ uint32_t smem_u32(const void* p) {
    uint32_t a;
    asm("{ .reg .u64 t; cvta.to.shared.u64 t, %1; cvt.u32.u64 %0, t; }" : "=r"(a) : "l"(p));
    return a;
}
__device__ __forceinline__ unsigned enc_f(float f) {
    unsigned u = __float_as_uint(f);
    return (u & 0x80000000u) ? ~u : (u | 0x80000000u);
}
__device__ __forceinline__ float dec_f(unsigned e) {
    unsigned u = (e & 0x80000000u) ? (e ^ 0x80000000u) : ~e;
    return __uint_as_float(u);
}
#define CPA(dst, src) \
    asm volatile("cp.async.cg.shared.global [%0], [%1], 16;" :: "r"(dst), "l"(src))
#define CP_COMMIT() asm volatile("cp.async.commit_group;" ::: "memory")
#define CP_WAIT(n)  asm volatile("cp.async.wait_group %0;" :: "n"(n) : "memory")

// ---------------------------------------------------------------------------
// Kernel 0: init rowmax
// ---------------------------------------------------------------------------
__global__ void init_rmax() { g_rmax[blockIdx.x * 256 + threadIdx.x] = 0u; }

// ---------------------------------------------------------------------------
// Kernel 1: fused QKV projection (fp32 GEMM), outputs split/rounded operands.
// ---------------------------------------------------------------------------
__global__ __launch_bounds__(256) void qkv_gemm(
    const float* __restrict__ X, const float* __restrict__ Wq,
    const float* __restrict__ Wk, const float* __restrict__ Wv)
{
    __shared__ float As[64][33];
    __shared__ float Bs[32][64];
    const int z = blockIdx.z;
    const float* W = (z == 0) ? Wq : (z == 1) ? Wk : Wv;
    const int bm = blockIdx.x * 64, bn = blockIdx.y * 64;
    const int t = threadIdx.x, tx = t & 15, ty = t >> 4;
    float acc[4][4] = {};

    for (int k0 = 0; k0 < HID; k0 += 32) {
        #pragma unroll
        for (int e = 0; e < 2; e++) {
            int f = e * 256 + t, m = f >> 3, k4 = f & 7;
            float4 v = *reinterpret_cast<const float4*>(X + (size_t)(bm + m) * HID + k0 + k4 * 4);
            As[m][k4 * 4 + 0] = v.x; As[m][k4 * 4 + 1] = v.y;
            As[m][k4 * 4 + 2] = v.z; As[m][k4 * 4 + 3] = v.w;
        }
        #pragma unroll
        for (int e = 0; e < 2; e++) {
            int f = e * 256 + t, k = f >> 4, n4 = f & 15;
            float4 v = *reinterpret_cast<const float4*>(W + (size_t)(k0 + k) * HID + bn + n4 * 4);
            *reinterpret_cast<float4*>(&Bs[k][n4 * 4]) = v;
        }
        __syncthreads();
        #pragma unroll
        for (int kk = 0; kk < 32; kk++) {
            float a0 = As[ty * 4 + 0][kk], a1 = As[ty * 4 + 1][kk];
            float a2 = As[ty * 4 + 2][kk], a3 = As[ty * 4 + 3][kk];
            float4 bb = *reinterpret_cast<const float4*>(&Bs[kk][tx * 4]);
            acc[0][0] += a0 * bb.x; acc[0][1] += a0 * bb.y; acc[0][2] += a0 * bb.z; acc[0][3] += a0 * bb.w;
            acc[1][0] += a1 * bb.x; acc[1][1] += a1 * bb.y; acc[1][2] += a1 * bb.z; acc[1][3] += a1 * bb.w;
            acc[2][0] += a2 * bb.x; acc[2][1] += a2 * bb.y; acc[2][2] += a2 * bb.z; acc[2][3] += a2 * bb.w;
            acc[3][0] += a3 * bb.x; acc[3][1] += a3 * bb.y; acc[3][2] += a3 * bb.z; acc[3][3] += a3 * bb.w;
        }
        __syncthreads();
    }

    if (z == 2) {
        #pragma unroll
        for (int r = 0; r < 4; r++) {
            size_t base = (size_t)(bm + ty * 4 + r) * HID + bn + tx * 4;
            #pragma unroll
            for (int c = 0; c < 4; c++) g_V[base + c] = tf32r(acc[r][c]);
        }
    } else {
        const float s = (z == 0) ? 0.0625f : 1.0f;       // fold 1/sqrt(256) into Q
        __nv_bfloat16* Gh = (z == 0) ? g_Qh : g_Kh;
        __nv_bfloat16* Gl = (z == 0) ? g_Ql : g_Kl;
        #pragma unroll
        for (int r = 0; r < 4; r++) {
            size_t base = (size_t)(bm + ty * 4 + r) * HID + bn + tx * 4;
            #pragma unroll
            for (int c = 0; c < 4; c++) {
                float v = acc[r][c] * s;
                __nv_bfloat16 h = __float2bfloat16_rn(v);
                Gh[base + c] = h;
                Gl[base + c] = __float2bfloat16_rn(v - __bfloat162float(h));
            }
        }
    }
}

// ---------------------------------------------------------------------------
// Kernel 2: S = Q K^T (bf16 x3) + per-row max.  Tile 64q x 64k, BK=64 chunks.
// grid (64 ktiles, 64 qtiles, 4 batch), 256 thr, 2 CTAs/SM.
// ---------------------------------------------------------------------------
#define SG_LDA   72                   // bf16 elems (144 B/row)
#define SG_MAT   9216                 // 64 * 144
#define SG_STG   36864                // 4 matrices / stage
#define SG_QH    0
#define SG_QL    9216
#define SG_KH    18432
#define SG_KL    27648
#define SG_S     73728                // float, ld 68 -> 17408 B
#define SG_LDS   68
#define SG_RM    91136                // 64 x 4 floats
#define SG_SMEM  92160

__global__ __launch_bounds__(256, 2) void s_gemm()
{
    extern __shared__ __align__(1024) char smem[];
    const uint32_t sm32 = smem_u32(smem);
    const int tid = threadIdx.x;
    const int w = tid >> 5;
    const int mw = w & 3, dw = w >> 2;
    const int b = blockIdx.z;
    const int q0 = blockIdx.y * 64, k0 = blockIdx.x * 64;

    const char* QhG = (const char*)(g_Qh + (size_t)(b * SEQ + q0) * HID);
    const char* QlG = (const char*)(g_Ql + (size_t)(b * SEQ + q0) * HID);
    const char* KhG = (const char*)(g_Kh + (size_t)(b * SEQ + k0) * HID);
    const char* KlG = (const char*)(g_Kl + (size_t)(b * SEQ + k0) * HID);

    auto loadchunk = [&](int c) {          // 64 rows x 128 B per matrix
        uint32_t base = sm32 + (c & 1) * SG_STG;
        #pragma unroll
        for (int e = 0; e < 2; e++) {
            int idx = e * 256 + tid, row = idx >> 3, col = idx & 7;
            size_t go = (size_t)row * 512 + c * 128 + col * 16;
            uint32_t so = row * 144 + col * 16;
            CPA(base + SG_QH + so, QhG + go);
            CPA(base + SG_QL + so, QlG + go);
            CPA(base + SG_KH + so, KhG + go);
            CPA(base + SG_KL + so, KlG + go);
        }
    };

    wmma::fragment<wmma::accumulator, 16, 16, 16, float> sacc[2];
    #pragma unroll
    for (int n = 0; n < 2; n++) wmma::fill_fragment(sacc[n], 0.0f);

    loadchunk(0);
    CP_COMMIT();
    for (int c = 0; c < 4; c++) {
        __syncthreads();
        if (c + 1 < 4) { loadchunk(c + 1); CP_COMMIT(); CP_WAIT(1); }
        else           { CP_WAIT(0); }
        __syncthreads();
        const char* base = smem + (c & 1) * SG_STG;
        const __nv_bfloat16* Qh = (const __nv_bfloat16*)(base + SG_QH);
        const __nv_bfloat16* Ql = (const __nv_bfloat16*)(base + SG_QL);
        const __nv_bfloat16* Kh = (const __nv_bfloat16*)(base + SG_KH);
        const __nv_bfloat16* Kl = (const __nv_bfloat16*)(base + SG_KL);
        wmma::fragment<wmma::matrix_a, 16, 16, 16, __nv_bfloat16, wmma::row_major> ah, al;
        wmma::fragment<wmma::matrix_b, 16, 16, 16, __nv_bfloat16, wmma::col_major> bh, bl;
        #pragma unroll
        for (int kk = 0; kk < 4; kk++) {
            wmma::load_matrix_sync(ah, Qh + mw * 16 * SG_LDA + kk * 16, SG_LDA);
            wmma::load_matrix_sync(al, Ql + mw * 16 * SG_LDA + kk * 16, SG_LDA);
            #pragma unroll
            for (int n = 0; n < 2; n++) {
                wmma::load_matrix_sync(bh, Kh + (dw * 32 + n * 16) * SG_LDA + kk * 16, SG_LDA);
                wmma::load_matrix_sync(bl, Kl + (dw * 32 + n * 16) * SG_LDA + kk * 16, SG_LDA);
                wmma::mma_sync(sacc[n], ah, bh, sacc[n]);
                wmma::mma_sync(sacc[n], ah, bl, sacc[n]);
                wmma::mma_sync(sacc[n], al, bh, sacc[n]);
            }
        }
    }

    float* Ss = (float*)(smem + SG_S);
    float* Rm = (float*)(smem + SG_RM);
    #pragma unroll
    for (int n = 0; n < 2; n++)
        wmma::store_matrix_sync(Ss + mw * 16 * SG_LDS + dw * 32 + n * 16, sacc[n],
                                SG_LDS, wmma::mem_row_major);
    __syncthreads();

    // row max + write S tile
    const int r = tid >> 2, g = tid & 3;
    {
        const float* srow = Ss + r * SG_LDS + g * 16;
        float m = srow[0];
        #pragma unroll
        for (int j = 1; j < 16; j++) m = fmaxf(m, srow[j]);
        Rm[r * 4 + g] = m;
    }
    __syncthreads();
    if (g == 0) {
        float m = fmaxf(fmaxf(Rm[r * 4 + 0], Rm[r * 4 + 1]),
                        fmaxf(Rm[r * 4 + 2], Rm[r * 4 + 3]));
        atomicMax(&g_rmax[b * SEQ + q0 + r], enc_f(m));
    }
    #pragma unroll
    for (int e = 0; e < 4; e++) {
        int idx = e * 256 + tid, row = idx >> 4, c4 = idx & 15;
        *reinterpret_cast<float4*>(
            g_S + ((size_t)b * SEQ + q0 + row) * SEQ + k0 + c4 * 4) =
            *reinterpret_cast<const float4*>(Ss + row * SG_LDS + c4 * 4);
    }
}

// ---------------------------------------------------------------------------
// Kernel 3: O = softmax(S) V.  64 q rows / CTA, 32-key tiles, tf32 PV.
// grid (64 qtiles, 4 batch), 256 thr, 2 CTAs/SM.
// ---------------------------------------------------------------------------
#define PV_LDP   36
#define PV_SBUF  9216                 // 64 * 144
#define PV_LDV   264
#define PV_VBUF  33792                // 32 * 1056
#define PV_S0    0
#define PV_S1    9216
#define PV_V0    18432
#define PV_V1    52224
#define PV_MS    86016
#define PV_RL    86272
#define PV_SMEM  87296
#define PV_LDO   264
#define PV_NT    (SEQ / 32)

__global__ __launch_bounds__(256, 2) void pv(float* __restrict__ out)
{
    extern __shared__ __align__(1024) char smem[];
    const uint32_t sm32 = smem_u32(smem);
    const int tid = threadIdx.x;
    const int w = tid >> 5;
    const int mw = w & 3, dw = w >> 2;
    const int r = tid >> 2, g = tid & 3;
    const int b = blockIdx.y;
    const int q0 = blockIdx.x * 64;

    const char* SG = (const char*)(g_S + ((size_t)b * SEQ + q0) * SEQ);
    const char* VG = (const char*)(g_V + (size_t)b * SEQ * HID);
    float* ms = (float*)(smem + PV_MS);
    float* Rl = (float*)(smem + PV_RL);

    if (tid < 64) ms[tid] = dec_f(g_rmax[b * SEQ + q0 + tid]);

    auto loadtile = [&](int kt) {
        uint32_t sb = sm32 + ((kt & 1) ? PV_S1 : PV_S0);
        uint32_t vb = sm32 + ((kt & 1) ? PV_V1 : PV_V0);
        #pragma unroll
        for (int e = 0; e < 2; e++) {       // S: 64 rows x 128 B
            int idx = e * 256 + tid, row = idx >> 3, col = idx & 7;
            CPA(sb + row * 144 + col * 16,
                SG + (size_t)row * (SEQ * 4) + (size_t)kt * 128 + col * 16);
        }
        #pragma unroll
        for (int e = 0; e < 8; e++) {       // V: 32 rows x 1024 B
            int idx = e * 256 + tid, row = idx >> 6, col = idx & 63;
            CPA(vb + row * 1056 + col * 16,
                VG + (size_t)(kt * 32 + row) * 1024 + col * 16);
        }
    };

    wmma::fragment<wmma::accumulator, 16, 16, 8, float> accO[8];
    #pragma unroll
    for (int n = 0; n < 8; n++) wmma::fill_fragment(accO[n], 0.0f);
    float lpart = 0.0f;

    loadtile(0);
    CP_COMMIT();
    for (int kt = 0; kt < PV_NT; kt++) {
        __syncthreads();
        if (kt + 1 < PV_NT) { loadtile(kt + 1); CP_COMMIT(); CP_WAIT(1); }
        else                { CP_WAIT(0); }
        __syncthreads();
        float* Ps = (float*)(smem + ((kt & 1) ? PV_S1 : PV_S0));
        const float* Vs = (const float*)(smem + ((kt & 1) ? PV_V1 : PV_V0));

        {   // softmax strip: row r, cols g*8..g*8+7
            float* prow = Ps + r * PV_LDP + g * 8;
            const float mr = ms[r];
            #pragma unroll
            for (int j = 0; j < 8; j++) {
                float p = tf32r(__expf(prow[j] - mr));
                lpart += p;
                prow[j] = p;
            }
        }
        __syncthreads();

        {   // PV accumulate (tf32)
            wmma::fragment<wmma::matrix_a, 16, 16, 8, wmma::precision::tf32, wmma::row_major> pa;
            wmma::fragment<wmma::matrix_b, 16, 16, 8, wmma::precision::tf32, wmma::row_major> vb;
            #pragma unroll
            for (int k4 = 0; k4 < 4; k4++) {
                wmma::load_matrix_sync(pa, Ps + mw * 16 * PV_LDP + k4 * 8, PV_LDP);
                #pragma unroll
                for (int n = 0; n < 8; n++) {
                    wmma::load_matrix_sync(vb, Vs + (k4 * 8) * PV_LDV + dw * 128 + n * 16, PV_LDV);
                    wmma::mma_sync(accO[n], pa, vb, accO[n]);
                }
            }
        }
    }

    // epilogue: stage O through smem (reuses V buffers), scale by 1/l, write
    Rl[r * 4 + g] = lpart;
    __syncthreads();
    float* Os = (float*)(smem + PV_V0);
    #pragma unroll
    for (int n = 0; n < 8; n++)
        wmma::store_matrix_sync(Os + mw * 16 * PV_LDO + dw * 128 + n * 16, accO[n],
                                PV_LDO, wmma::mem_row_major);
    __syncthreads();
    const float linv = 1.0f / (Rl[r * 4 + 0] + Rl[r * 4 + 1] + Rl[r * 4 + 2] + Rl[r * 4 + 3]);
    float* orow = out + ((size_t)b * SEQ + q0 + r) * HID + g * 64;
    const float* srow = Os + r * PV_LDO + g * 64;
    #pragma unroll
    for (int j = 0; j < 16; j++) {
        float4 v = *reinterpret_cast<const float4*>(srow + j * 4);
        v.x *= linv; v.y *= linv; v.z *= linv; v.w *= linv;
        *reinterpret_cast<float4*>(orow + j * 4) = v;
    }
}

// ---------------------------------------------------------------------------
extern "C" void kernel_launch(void* const* d_in, const int* in_sizes, int n_in,
                              void* d_out, int out_size)
{
    const float* X  = (const float*)d_in[0];
    const float* Wq = (const float*)d_in[1];
    const float* Wk = (const float*)d_in[2];
    const float* Wv = (const float*)d_in[3];
    // d_in[4] = lengths (unused by the reference module)
    float* out = (float*)d_out;

    cudaFuncSetAttribute(s_gemm, cudaFuncAttributeMaxDynamicSharedMemorySize, SG_SMEM);
    cudaFuncSetAttribute(pv,     cudaFuncAttributeMaxDynamicSharedMemorySize, PV_SMEM);

    init_rmax<<<MTOT / 256, 256>>>();
    qkv_gemm<<<dim3(MTOT / 64, HID / 64, 3), 256>>>(X, Wq, Wk, Wv);
    s_gemm<<<dim3(SEQ / 64, SEQ / 64, BATCH), 256, SG_SMEM>>>();
    pv<<<dim3(SEQ / 64, BATCH), 256, PV_SMEM>>>(out);
}

// round 9
// speedup vs baseline: 4.1599x; 1.6568x over previous
#include <cuda_runtime.h>
#include <cuda_bf16.h>
#include <cuda_fp16.h>
#include <mma.h>
#include <cstdint>
using namespace nvcuda;

#define BATCH 4
#define SEQ   4096
#define HID   256
#define MTOT  (BATCH * SEQ)

__device__ __align__(16) __nv_bfloat16 g_Qh[MTOT * HID];
__device__ __align__(16) __nv_bfloat16 g_Ql[MTOT * HID];
__device__ __align__(16) __nv_bfloat16 g_Kh[MTOT * HID];
__device__ __align__(16) __nv_bfloat16 g_Kl[MTOT * HID];
__device__ __align__(16) __half        g_Vh[MTOT * HID];
__device__ __align__(16) float         g_S [(size_t)BATCH * SEQ * SEQ];   // 256 MB
__device__ unsigned g_rmax[MTOT];

__device__ __forceinline__ uint32_t smem_u32(const void* p) {
    uint32_t a;
    asm("{ .reg .u64 t; cvta.to.shared.u64 t, %1; cvt.u32.u64 %0, t; }" : "=r"(a) : "l"(p));
    return a;
}
__device__ __forceinline__ unsigned enc_f(float f) {
    unsigned u = __float_as_uint(f);
    return (u & 0x80000000u) ? ~u : (u | 0x80000000u);
}
__device__ __forceinline__ float dec_f(unsigned e) {
    unsigned u = (e & 0x80000000u) ? (e ^ 0x80000000u) : ~e;
    return __uint_as_float(u);
}
#define CPA(dst, src) \
    asm volatile("cp.async.cg.shared.global [%0], [%1], 16;" :: "r"(dst), "l"(src))
#define CP_COMMIT() asm volatile("cp.async.commit_group;" ::: "memory")
#define CP_WAIT(n)  asm volatile("cp.async.wait_group %0;" :: "n"(n) : "memory")

// ---------------------------------------------------------------------------
__global__ void init_rmax() { g_rmax[blockIdx.x * 256 + threadIdx.x] = 0u; }

// ---------------------------------------------------------------------------
// Kernel 1: fused QKV projection (fp32 GEMM), formatted outputs.
// ---------------------------------------------------------------------------
__global__ __launch_bounds__(256) void qkv_gemm(
    const float* __restrict__ X, const float* __restrict__ Wq,
    const float* __restrict__ Wk, const float* __restrict__ Wv)
{
    __shared__ float As[64][33];
    __shared__ float Bs[32][64];
    const int z = blockIdx.z;
    const float* W = (z == 0) ? Wq : (z == 1) ? Wk : Wv;
    const int bm = blockIdx.x * 64, bn = blockIdx.y * 64;
    const int t = threadIdx.x, tx = t & 15, ty = t >> 4;
    float acc[4][4] = {};

    for (int k0 = 0; k0 < HID; k0 += 32) {
        #pragma unroll
        for (int e = 0; e < 2; e++) {
            int f = e * 256 + t, m = f >> 3, k4 = f & 7;
            float4 v = *reinterpret_cast<const float4*>(X + (size_t)(bm + m) * HID + k0 + k4 * 4);
            As[m][k4 * 4 + 0] = v.x; As[m][k4 * 4 + 1] = v.y;
            As[m][k4 * 4 + 2] = v.z; As[m][k4 * 4 + 3] = v.w;
        }
        #pragma unroll
        for (int e = 0; e < 2; e++) {
            int f = e * 256 + t, k = f >> 4, n4 = f & 15;
            float4 v = *reinterpret_cast<const float4*>(W + (size_t)(k0 + k) * HID + bn + n4 * 4);
            *reinterpret_cast<float4*>(&Bs[k][n4 * 4]) = v;
        }
        __syncthreads();
        #pragma unroll
        for (int kk = 0; kk < 32; kk++) {
            float a0 = As[ty * 4 + 0][kk], a1 = As[ty * 4 + 1][kk];
            float a2 = As[ty * 4 + 2][kk], a3 = As[ty * 4 + 3][kk];
            float4 bb = *reinterpret_cast<const float4*>(&Bs[kk][tx * 4]);
            acc[0][0] += a0 * bb.x; acc[0][1] += a0 * bb.y; acc[0][2] += a0 * bb.z; acc[0][3] += a0 * bb.w;
            acc[1][0] += a1 * bb.x; acc[1][1] += a1 * bb.y; acc[1][2] += a1 * bb.z; acc[1][3] += a1 * bb.w;
            acc[2][0] += a2 * bb.x; acc[2][1] += a2 * bb.y; acc[2][2] += a2 * bb.z; acc[2][3] += a2 * bb.w;
            acc[3][0] += a3 * bb.x; acc[3][1] += a3 * bb.y; acc[3][2] += a3 * bb.z; acc[3][3] += a3 * bb.w;
        }
        __syncthreads();
    }

    if (z == 2) {
        #pragma unroll
        for (int r = 0; r < 4; r++) {
            size_t base = (size_t)(bm + ty * 4 + r) * HID + bn + tx * 4;
            #pragma unroll
            for (int c = 0; c < 4; c++) g_Vh[base + c] = __float2half_rn(acc[r][c]);
        }
    } else {
        const float s = (z == 0) ? 0.0625f : 1.0f;       // fold 1/sqrt(256) into Q
        __nv_bfloat16* Gh = (z == 0) ? g_Qh : g_Kh;
        __nv_bfloat16* Gl = (z == 0) ? g_Ql : g_Kl;
        #pragma unroll
        for (int r = 0; r < 4; r++) {
            size_t base = (size_t)(bm + ty * 4 + r) * HID + bn + tx * 4;
            #pragma unroll
            for (int c = 0; c < 4; c++) {
                float v = acc[r][c] * s;
                __nv_bfloat16 h = __float2bfloat16_rn(v);
                Gh[base + c] = h;
                Gl[base + c] = __float2bfloat16_rn(v - __bfloat162float(h));
            }
        }
    }
}

// ---------------------------------------------------------------------------
// Kernel 2: S = Q K^T (bf16 x3) + per-row max.  Tile 128q x 64k, BK=32 x2buf.
// grid (64 k, 32 q, 4 b), 256 thr, 2 CTAs/SM.  Warp tile 32x32.
// ---------------------------------------------------------------------------
#define SGA_LD  40                    // bf16 elems (80 B/row)
#define SG_QH   0
#define SG_QL   10240
#define SG_KH   20480
#define SG_KL   25600
#define SG_STG  30720
#define SG_S    61440                 // f32, ld 68
#define SG_LDS  68
#define SG_RM   96256                 // 128 x 2 floats
#define SG_SMEM 97280

__global__ __launch_bounds__(256, 2) void s_gemm()
{
    extern __shared__ __align__(1024) char smem[];
    const uint32_t sm32 = smem_u32(smem);
    const int tid = threadIdx.x;
    const int w = tid >> 5;
    const int mw = w >> 1, dw = w & 1;   // 4 row-warps x 2 col-warps
    const int b = blockIdx.z;
    const int q0 = blockIdx.y * 128, k0 = blockIdx.x * 64;

    const char* QhG = (const char*)(g_Qh + (size_t)(b * SEQ + q0) * HID);
    const char* QlG = (const char*)(g_Ql + (size_t)(b * SEQ + q0) * HID);
    const char* KhG = (const char*)(g_Kh + (size_t)(b * SEQ + k0) * HID);
    const char* KlG = (const char*)(g_Kl + (size_t)(b * SEQ + k0) * HID);

    auto loadchunk = [&](int c) {            // BK=32 -> 64 B per row
        uint32_t base = sm32 + (c & 1) * SG_STG;
        const int row = tid >> 2, col = tid & 3;
        const uint32_t so = row * 80 + col * 16;
        const size_t go = (size_t)row * 512 + c * 64 + col * 16;
        CPA(base + SG_QH + so, QhG + go);
        CPA(base + SG_QH + 64 * 80 + so, QhG + 64 * 512 + go);
        CPA(base + SG_QL + so, QlG + go);
        CPA(base + SG_QL + 64 * 80 + so, QlG + 64 * 512 + go);
        CPA(base + SG_KH + so, KhG + go);
        CPA(base + SG_KL + so, KlG + go);
    };

    wmma::fragment<wmma::accumulator, 16, 16, 16, float> sacc[2][2];
    #pragma unroll
    for (int m = 0; m < 2; m++)
        #pragma unroll
        for (int n = 0; n < 2; n++) wmma::fill_fragment(sacc[m][n], 0.0f);

    loadchunk(0);
    CP_COMMIT();
    for (int c = 0; c < 8; c++) {
        __syncthreads();
        if (c + 1 < 8) { loadchunk(c + 1); CP_COMMIT(); CP_WAIT(1); }
        else           { CP_WAIT(0); }
        __syncthreads();
        const char* base = smem + (c & 1) * SG_STG;
        const __nv_bfloat16* Qh = (const __nv_bfloat16*)(base + SG_QH);
        const __nv_bfloat16* Ql = (const __nv_bfloat16*)(base + SG_QL);
        const __nv_bfloat16* Kh = (const __nv_bfloat16*)(base + SG_KH);
        const __nv_bfloat16* Kl = (const __nv_bfloat16*)(base + SG_KL);
        wmma::fragment<wmma::matrix_a, 16, 16, 16, __nv_bfloat16, wmma::row_major> ah[2], al[2];
        wmma::fragment<wmma::matrix_b, 16, 16, 16, __nv_bfloat16, wmma::col_major> bh, bl;
        #pragma unroll
        for (int kk = 0; kk < 2; kk++) {
            #pragma unroll
            for (int m = 0; m < 2; m++) {
                wmma::load_matrix_sync(ah[m], Qh + (mw * 32 + m * 16) * SGA_LD + kk * 16, SGA_LD);
                wmma::load_matrix_sync(al[m], Ql + (mw * 32 + m * 16) * SGA_LD + kk * 16, SGA_LD);
            }
            #pragma unroll
            for (int n = 0; n < 2; n++) {
                wmma::load_matrix_sync(bh, Kh + (dw * 32 + n * 16) * SGA_LD + kk * 16, SGA_LD);
                wmma::load_matrix_sync(bl, Kl + (dw * 32 + n * 16) * SGA_LD + kk * 16, SGA_LD);
                #pragma unroll
                for (int m = 0; m < 2; m++) {
                    wmma::mma_sync(sacc[m][n], ah[m], bh, sacc[m][n]);
                    wmma::mma_sync(sacc[m][n], ah[m], bl, sacc[m][n]);
                    wmma::mma_sync(sacc[m][n], al[m], bh, sacc[m][n]);
                }
            }
        }
    }

    float* Ss = (float*)(smem + SG_S);
    float* Rm = (float*)(smem + SG_RM);
    #pragma unroll
    for (int m = 0; m < 2; m++)
        #pragma unroll
        for (int n = 0; n < 2; n++)
            wmma::store_matrix_sync(Ss + (mw * 32 + m * 16) * SG_LDS + dw * 32 + n * 16,
                                    sacc[m][n], SG_LDS, wmma::mem_row_major);
    __syncthreads();

    {   // row max over 128 rows: thread pair per row
        const int r = tid >> 1, g = tid & 1;
        const float* srow = Ss + r * SG_LDS + g * 32;
        float m = srow[0];
        #pragma unroll
        for (int j = 1; j < 32; j++) m = fmaxf(m, srow[j]);
        Rm[r * 2 + g] = m;
        __syncthreads();
        if (g == 0)
            atomicMax(&g_rmax[b * SEQ + q0 + r], enc_f(fmaxf(Rm[r * 2], Rm[r * 2 + 1])));
    }
    #pragma unroll
    for (int e = 0; e < 8; e++) {
        int idx = e * 256 + tid, row = idx >> 4, c4 = idx & 15;
        *reinterpret_cast<float4*>(
            g_S + ((size_t)b * SEQ + q0 + row) * SEQ + k0 + c4 * 4) =
            *reinterpret_cast<const float4*>(Ss + row * SG_LDS + c4 * 4);
    }
}

// ---------------------------------------------------------------------------
// Kernel 3: O = softmax(S) V, fp16 HMMA.  64 q rows/CTA, KT=64 key tiles.
// grid (64, 4), 256 thr, 2 CTAs/SM.  Warp tile 32x64 (2x4 warps).
// ---------------------------------------------------------------------------
#define PV_SLD  68                    // floats (272 B/row)
#define PV_S0   0
#define PV_S1   17408
#define PV_VLD  264                   // halves (528 B/row)
#define PV_V0   34816
#define PV_V1   68608
#define PV_P    102400                // halves, ld 72 (144 B/row)
#define PV_PLD  72
#define PV_MS   111616
#define PV_RL   111872
#define PV_SMEM 112896
#define PV_OLD  264                   // f32 staging ld
#define PV_NT   (SEQ / 64)

__global__ __launch_bounds__(256, 2) void pv(float* __restrict__ out)
{
    extern __shared__ __align__(1024) char smem[];
    const uint32_t sm32 = smem_u32(smem);
    const int tid = threadIdx.x;
    const int w = tid >> 5;
    const int mw2 = w >> 2, dv = w & 3;
    const int r = tid >> 2, g = tid & 3;
    const int b = blockIdx.y;
    const int q0 = blockIdx.x * 64;

    const char* SG = (const char*)(g_S + ((size_t)b * SEQ + q0) * SEQ);
    const char* VG = (const char*)(g_Vh + (size_t)b * SEQ * HID);
    float* ms = (float*)(smem + PV_MS);
    float* Rl = (float*)(smem + PV_RL);

    if (tid < 64) ms[tid] = dec_f(g_rmax[b * SEQ + q0 + tid]);

    auto loadtile = [&](int kt) {
        uint32_t sb = sm32 + ((kt & 1) ? PV_S1 : PV_S0);
        uint32_t vb = sm32 + ((kt & 1) ? PV_V1 : PV_V0);
        #pragma unroll
        for (int e = 0; e < 4; e++) {          // S: 64 rows x 256 B
            int idx = e * 256 + tid, row = idx >> 4, col = idx & 15;
            CPA(sb + row * 272 + col * 16,
                SG + (size_t)row * (SEQ * 4) + (size_t)kt * 256 + col * 16);
        }
        #pragma unroll
        for (int e = 0; e < 8; e++) {          // V: 64 rows x 512 B (fp16)
            int idx = e * 256 + tid, row = idx >> 5, col = idx & 31;
            CPA(vb + row * 528 + col * 16,
                VG + (size_t)(kt * 64 + row) * 512 + col * 16);
        }
    };

    wmma::fragment<wmma::accumulator, 16, 16, 16, float> accO[2][4];
    #pragma unroll
    for (int m = 0; m < 2; m++)
        #pragma unroll
        for (int n = 0; n < 4; n++) wmma::fill_fragment(accO[m][n], 0.0f);
    float lpart = 0.0f;
    const float L2E = 1.44269504f;

    loadtile(0);
    CP_COMMIT();
    for (int kt = 0; kt < PV_NT; kt++) {
        __syncthreads();
        if (kt + 1 < PV_NT) { loadtile(kt + 1); CP_COMMIT(); CP_WAIT(1); }
        else                { CP_WAIT(0); }
        __syncthreads();
        const char* Sb = smem + ((kt & 1) ? PV_S1 : PV_S0);
        const __half* Vs = (const __half*)(smem + ((kt & 1) ? PV_V1 : PV_V0));

        {   // softmax strip: row r, 16 cols at g*16; P as fp16, l from rounded p
            const float4* srow = (const float4*)(Sb + r * 272 + g * 64);
            __half2* prow = (__half2*)(smem + PV_P + r * 144 + g * 32);
            const float mr = ms[r];
            #pragma unroll
            for (int j4 = 0; j4 < 4; j4++) {
                float4 s4 = srow[j4];
                float p0 = exp2f((s4.x - mr) * L2E);
                float p1 = exp2f((s4.y - mr) * L2E);
                float p2 = exp2f((s4.z - mr) * L2E);
                float p3 = exp2f((s4.w - mr) * L2E);
                __half2 h01 = __floats2half2_rn(p0, p1);
                __half2 h23 = __floats2half2_rn(p2, p3);
                float2 b01 = __half22float2(h01);
                float2 b23 = __half22float2(h23);
                lpart += (b01.x + b01.y) + (b23.x + b23.y);
                prow[j4 * 2 + 0] = h01;
                prow[j4 * 2 + 1] = h23;
            }
        }
        __syncthreads();

        {   // PV accumulate (fp16 x fp16 -> fp32)
            const __half* Ps = (const __half*)(smem + PV_P);
            wmma::fragment<wmma::matrix_a, 16, 16, 16, __half, wmma::row_major> pa[2];
            wmma::fragment<wmma::matrix_b, 16, 16, 16, __half, wmma::row_major> vb;
            #pragma unroll
            for (int kk = 0; kk < 4; kk++) {
                #pragma unroll
                for (int m = 0; m < 2; m++)
                    wmma::load_matrix_sync(pa[m], Ps + (mw2 * 32 + m * 16) * PV_PLD + kk * 16, PV_PLD);
                #pragma unroll
                for (int n = 0; n < 4; n++) {
                    wmma::load_matrix_sync(vb, Vs + (kk * 16) * PV_VLD + dv * 64 + n * 16, PV_VLD);
                    #pragma unroll
                    for (int m = 0; m < 2; m++)
                        wmma::mma_sync(accO[m][n], pa[m], vb, accO[m][n]);
                }
            }
        }
    }

    // epilogue: stage O via smem (reuses V area), scale by 1/l, write out
    Rl[r * 4 + g] = lpart;
    __syncthreads();
    float* Os = (float*)(smem + PV_V0);
    #pragma unroll
    for (int m = 0; m < 2; m++)
        #pragma unroll
        for (int n = 0; n < 4; n++)
            wmma::store_matrix_sync(Os + (mw2 * 32 + m * 16) * PV_OLD + dv * 64 + n * 16,
                                    accO[m][n], PV_OLD, wmma::mem_row_major);
    __syncthreads();
    const float linv = 1.0f / (Rl[r * 4 + 0] + Rl[r * 4 + 1] + Rl[r * 4 + 2] + Rl[r * 4 + 3]);
    float* orow = out + ((size_t)b * SEQ + q0 + r) * HID + g * 64;
    const float* srow = Os + r * PV_OLD + g * 64;
    #pragma unroll
    for (int j = 0; j < 16; j++) {
        float4 v = *reinterpret_cast<const float4*>(srow + j * 4);
        v.x *= linv; v.y *= linv; v.z *= linv; v.w *= linv;
        *reinterpret_cast<float4*>(orow + j * 4) = v;
    }
}

// ---------------------------------------------------------------------------
extern "C" void kernel_launch(void* const* d_in, const int* in_sizes, int n_in,
                              void* d_out, int out_size)
{
    const float* X  = (const float*)d_in[0];
    const float* Wq = (const float*)d_in[1];
    const float* Wk = (const float*)d_in[2];
    const float* Wv = (const float*)d_in[3];
    // d_in[4] = lengths (unused by the reference module)
    float* out = (float*)d_out;

    cudaFuncSetAttribute(s_gemm, cudaFuncAttributeMaxDynamicSharedMemorySize, SG_SMEM);
    cudaFuncSetAttribute(pv,     cudaFuncAttributeMaxDynamicSharedMemorySize, PV_SMEM);

    init_rmax<<<MTOT / 256, 256>>>();
    qkv_gemm<<<dim3(MTOT / 64, HID / 64, 3), 256>>>(X, Wq, Wk, Wv);
    s_gemm<<<dim3(SEQ / 64, SEQ / 128, BATCH), 256, SG_SMEM>>>();
    pv<<<dim3(SEQ / 64, BATCH), 256, PV_SMEM>>>(out);
}

// round 10
// speedup vs baseline: 4.5850x; 1.1022x over previous
#include <cuda_runtime.h>
#include <cuda_bf16.h>
#include <cuda_fp16.h>
#include <mma.h>
#include <cstdint>
using namespace nvcuda;

#define BATCH 4
#define SEQ   4096
#define HID   256
#define MTOT  (BATCH * SEQ)

__device__ __align__(16) __nv_bfloat16 g_Qh[MTOT * HID];
__device__ __align__(16) __nv_bfloat16 g_Ql[MTOT * HID];
__device__ __align__(16) __nv_bfloat16 g_Kh[MTOT * HID];
__device__ __align__(16) __nv_bfloat16 g_Kl[MTOT * HID];
__device__ __align__(16) __half        g_Vh[MTOT * HID];
__device__ __align__(16) float         g_S [(size_t)BATCH * SEQ * SEQ];   // 256 MB
__device__ unsigned g_rmax[MTOT];

__device__ __forceinline__ uint32_t smem_u32(const void* p) {
    uint32_t a;
    asm("{ .reg .u64 t; cvta.to.shared.u64 t, %1; cvt.u32.u64 %0, t; }" : "=r"(a) : "l"(p));
    return a;
}
__device__ __forceinline__ unsigned enc_f(float f) {
    unsigned u = __float_as_uint(f);
    return (u & 0x80000000u) ? ~u : (u | 0x80000000u);
}
__device__ __forceinline__ float dec_f(unsigned e) {
    unsigned u = (e & 0x80000000u) ? (e ^ 0x80000000u) : ~e;
    return __uint_as_float(u);
}
#define CPA(dst, src) \
    asm volatile("cp.async.cg.shared.global [%0], [%1], 16;" :: "r"(dst), "l"(src))
#define CP_COMMIT() asm volatile("cp.async.commit_group;" ::: "memory")
#define CP_WAIT(n)  asm volatile("cp.async.wait_group %0;" :: "n"(n) : "memory")

// ---------------------------------------------------------------------------
__global__ void init_rmax() { g_rmax[blockIdx.x * 256 + threadIdx.x] = 0u; }

// ---------------------------------------------------------------------------
// Kernel 1: fused QKV projection (fp32 GEMM), formatted outputs.
// ---------------------------------------------------------------------------
__global__ __launch_bounds__(256) void qkv_gemm(
    const float* __restrict__ X, const float* __restrict__ Wq,
    const float* __restrict__ Wk, const float* __restrict__ Wv)
{
    __shared__ float As[64][33];
    __shared__ float Bs[32][64];
    const int z = blockIdx.z;
    const float* W = (z == 0) ? Wq : (z == 1) ? Wk : Wv;
    const int bm = blockIdx.x * 64, bn = blockIdx.y * 64;
    const int t = threadIdx.x, tx = t & 15, ty = t >> 4;
    float acc[4][4] = {};

    for (int k0 = 0; k0 < HID; k0 += 32) {
        #pragma unroll
        for (int e = 0; e < 2; e++) {
            int f = e * 256 + t, m = f >> 3, k4 = f & 7;
            float4 v = *reinterpret_cast<const float4*>(X + (size_t)(bm + m) * HID + k0 + k4 * 4);
            As[m][k4 * 4 + 0] = v.x; As[m][k4 * 4 + 1] = v.y;
            As[m][k4 * 4 + 2] = v.z; As[m][k4 * 4 + 3] = v.w;
        }
        #pragma unroll
        for (int e = 0; e < 2; e++) {
            int f = e * 256 + t, k = f >> 4, n4 = f & 15;
            float4 v = *reinterpret_cast<const float4*>(W + (size_t)(k0 + k) * HID + bn + n4 * 4);
            *reinterpret_cast<float4*>(&Bs[k][n4 * 4]) = v;
        }
        __syncthreads();
        #pragma unroll
        for (int kk = 0; kk < 32; kk++) {
            float a0 = As[ty * 4 + 0][kk], a1 = As[ty * 4 + 1][kk];
            float a2 = As[ty * 4 + 2][kk], a3 = As[ty * 4 + 3][kk];
            float4 bb = *reinterpret_cast<const float4*>(&Bs[kk][tx * 4]);
            acc[0][0] += a0 * bb.x; acc[0][1] += a0 * bb.y; acc[0][2] += a0 * bb.z; acc[0][3] += a0 * bb.w;
            acc[1][0] += a1 * bb.x; acc[1][1] += a1 * bb.y; acc[1][2] += a1 * bb.z; acc[1][3] += a1 * bb.w;
            acc[2][0] += a2 * bb.x; acc[2][1] += a2 * bb.y; acc[2][2] += a2 * bb.z; acc[2][3] += a2 * bb.w;
            acc[3][0] += a3 * bb.x; acc[3][1] += a3 * bb.y; acc[3][2] += a3 * bb.z; acc[3][3] += a3 * bb.w;
        }
        __syncthreads();
    }

    if (z == 2) {
        #pragma unroll
        for (int r = 0; r < 4; r++) {
            size_t base = (size_t)(bm + ty * 4 + r) * HID + bn + tx * 4;
            #pragma unroll
            for (int c = 0; c < 4; c++) g_Vh[base + c] = __float2half_rn(acc[r][c]);
        }
    } else {
        const float s = (z == 0) ? 0.0625f : 1.0f;       // fold 1/sqrt(256) into Q
        __nv_bfloat16* Gh = (z == 0) ? g_Qh : g_Kh;
        __nv_bfloat16* Gl = (z == 0) ? g_Ql : g_Kl;
        #pragma unroll
        for (int r = 0; r < 4; r++) {
            size_t base = (size_t)(bm + ty * 4 + r) * HID + bn + tx * 4;
            #pragma unroll
            for (int c = 0; c < 4; c++) {
                float v = acc[r][c] * s;
                __nv_bfloat16 h = __float2bfloat16_rn(v);
                Gh[base + c] = h;
                Gl[base + c] = __float2bfloat16_rn(v - __bfloat162float(h));
            }
        }
    }
}

// ---------------------------------------------------------------------------
// Kernel 2: S = Q K^T (bf16 x3) + per-row max.
// CTA tile 128q x 128k, BK=32 double-buffered, 256 thr (4x2 warps, 32x64/warp).
// S staging reuses the stage buffers. 2 CTAs/SM.
// ---------------------------------------------------------------------------
#define SGA_LD   40                    // bf16 elems per row (80 B)
#define SG_QH    0
#define SG_QL    10240
#define SG_KH    20480
#define SG_KL    30720
#define SG_STG   40960                 // bytes per stage
#define SG_LDS   132                   // f32 elems (S staging ld)
#define SG_RM    81920                 // 128 x 2 floats
#define SG_SMEM  82944

__global__ __launch_bounds__(256, 2) void s_gemm()
{
    extern __shared__ __align__(1024) char smem[];
    const uint32_t sm32 = smem_u32(smem);
    const int tid = threadIdx.x;
    const int w = tid >> 5;
    const int mw = w >> 1, dw = w & 1;   // 4 row-warps (32 rows) x 2 col-warps (64 cols)
    const int b = blockIdx.z;
    const int q0 = blockIdx.y * 128, k0 = blockIdx.x * 128;

    const char* QhG = (const char*)(g_Qh + (size_t)(b * SEQ + q0) * HID);
    const char* QlG = (const char*)(g_Ql + (size_t)(b * SEQ + q0) * HID);
    const char* KhG = (const char*)(g_Kh + (size_t)(b * SEQ + k0) * HID);
    const char* KlG = (const char*)(g_Kl + (size_t)(b * SEQ + k0) * HID);

    auto loadchunk = [&](int c) {            // 128 rows x 64 B per matrix
        uint32_t base = sm32 + (c & 1) * SG_STG;
        #pragma unroll
        for (int e = 0; e < 2; e++) {
            int idx = e * 256 + tid;
            int row = idx >> 2, col = idx & 3;
            uint32_t so = row * 80 + col * 16;
            size_t   go = (size_t)row * 512 + c * 64 + col * 16;
            CPA(base + SG_QH + so, QhG + go);
            CPA(base + SG_QL + so, QlG + go);
            CPA(base + SG_KH + so, KhG + go);
            CPA(base + SG_KL + so, KlG + go);
        }
    };

    wmma::fragment<wmma::accumulator, 16, 16, 16, float> sacc[2][4];
    #pragma unroll
    for (int m = 0; m < 2; m++)
        #pragma unroll
        for (int n = 0; n < 4; n++) wmma::fill_fragment(sacc[m][n], 0.0f);

    loadchunk(0);
    CP_COMMIT();
    for (int c = 0; c < 8; c++) {
        __syncthreads();
        if (c + 1 < 8) { loadchunk(c + 1); CP_COMMIT(); CP_WAIT(1); }
        else           { CP_WAIT(0); }
        __syncthreads();
        const char* base = smem + (c & 1) * SG_STG;
        const __nv_bfloat16* Qh = (const __nv_bfloat16*)(base + SG_QH);
        const __nv_bfloat16* Ql = (const __nv_bfloat16*)(base + SG_QL);
        const __nv_bfloat16* Kh = (const __nv_bfloat16*)(base + SG_KH);
        const __nv_bfloat16* Kl = (const __nv_bfloat16*)(base + SG_KL);
        wmma::fragment<wmma::matrix_a, 16, 16, 16, __nv_bfloat16, wmma::row_major> ah[2], al[2];
        wmma::fragment<wmma::matrix_b, 16, 16, 16, __nv_bfloat16, wmma::col_major> bh, bl;
        #pragma unroll
        for (int kk = 0; kk < 2; kk++) {
            #pragma unroll
            for (int m = 0; m < 2; m++) {
                wmma::load_matrix_sync(ah[m], Qh + (mw * 32 + m * 16) * SGA_LD + kk * 16, SGA_LD);
                wmma::load_matrix_sync(al[m], Ql + (mw * 32 + m * 16) * SGA_LD + kk * 16, SGA_LD);
            }
            #pragma unroll
            for (int n = 0; n < 4; n++) {
                wmma::load_matrix_sync(bh, Kh + (dw * 64 + n * 16) * SGA_LD + kk * 16, SGA_LD);
                wmma::load_matrix_sync(bl, Kl + (dw * 64 + n * 16) * SGA_LD + kk * 16, SGA_LD);
                #pragma unroll
                for (int m = 0; m < 2; m++) {
                    wmma::mma_sync(sacc[m][n], ah[m], bh, sacc[m][n]);
                    wmma::mma_sync(sacc[m][n], ah[m], bl, sacc[m][n]);
                    wmma::mma_sync(sacc[m][n], al[m], bh, sacc[m][n]);
                }
            }
        }
    }

    // ---- stage S into smem (reuses stage buffers) ----
    __syncthreads();                     // all compute reads of stages done
    float* Ss = (float*)smem;
    float* Rm = (float*)(smem + SG_RM);
    #pragma unroll
    for (int m = 0; m < 2; m++)
        #pragma unroll
        for (int n = 0; n < 4; n++)
            wmma::store_matrix_sync(Ss + (mw * 32 + m * 16) * SG_LDS + dw * 64 + n * 16,
                                    sacc[m][n], SG_LDS, wmma::mem_row_major);
    __syncthreads();

    {   // row max: 2 threads per row (64 cols each)
        const int r = tid >> 1, g = tid & 1;
        const float* srow = Ss + r * SG_LDS + g * 64;
        float m = srow[0];
        #pragma unroll
        for (int j = 1; j < 64; j++) m = fmaxf(m, srow[j]);
        Rm[r * 2 + g] = m;
        __syncthreads();
        if (g == 0)
            atomicMax(&g_rmax[b * SEQ + q0 + r], enc_f(fmaxf(Rm[r * 2], Rm[r * 2 + 1])));
    }
    #pragma unroll
    for (int e = 0; e < 16; e++) {
        int idx = e * 256 + tid, row = idx >> 5, c4 = idx & 31;
        *reinterpret_cast<float4*>(
            g_S + ((size_t)b * SEQ + q0 + row) * SEQ + k0 + c4 * 4) =
            *reinterpret_cast<const float4*>(Ss + row * SG_LDS + c4 * 4);
    }
}

// ---------------------------------------------------------------------------
// Kernel 3: O = softmax(S) V, fp16 HMMA.  64 q rows/CTA, KT=64 key tiles.
// grid (64, 4), 256 thr, 2 CTAs/SM.  Warp tile 32x64 (2x4 warps).
// ---------------------------------------------------------------------------
#define PV_SLD  68                    // floats (272 B/row)
#define PV_S0   0
#define PV_S1   17408
#define PV_VLD  264                   // halves (528 B/row)
#define PV_V0   34816
#define PV_V1   68608
#define PV_P    102400                // halves, ld 72 (144 B/row)
#define PV_PLD  72
#define PV_MS   111616
#define PV_RL   111872
#define PV_SMEM 112896
#define PV_OLD  264                   // f32 staging ld
#define PV_NT   (SEQ / 64)

__global__ __launch_bounds__(256, 2) void pv(float* __restrict__ out)
{
    extern __shared__ __align__(1024) char smem[];
    const uint32_t sm32 = smem_u32(smem);
    const int tid = threadIdx.x;
    const int w = tid >> 5;
    const int mw2 = w >> 2, dv = w & 3;
    const int r = tid >> 2, g = tid & 3;
    const int b = blockIdx.y;
    const int q0 = blockIdx.x * 64;

    const char* SG = (const char*)(g_S + ((size_t)b * SEQ + q0) * SEQ);
    const char* VG = (const char*)(g_Vh + (size_t)b * SEQ * HID);
    float* ms = (float*)(smem + PV_MS);
    float* Rl = (float*)(smem + PV_RL);

    if (tid < 64) ms[tid] = dec_f(g_rmax[b * SEQ + q0 + tid]);

    auto loadtile = [&](int kt) {
        uint32_t sb = sm32 + ((kt & 1) ? PV_S1 : PV_S0);
        uint32_t vb = sm32 + ((kt & 1) ? PV_V1 : PV_V0);
        #pragma unroll
        for (int e = 0; e < 4; e++) {          // S: 64 rows x 256 B
            int idx = e * 256 + tid, row = idx >> 4, col = idx & 15;
            CPA(sb + row * 272 + col * 16,
                SG + (size_t)row * (SEQ * 4) + (size_t)kt * 256 + col * 16);
        }
        #pragma unroll
        for (int e = 0; e < 8; e++) {          // V: 64 rows x 512 B (fp16)
            int idx = e * 256 + tid, row = idx >> 5, col = idx & 31;
            CPA(vb + row * 528 + col * 16,
                VG + (size_t)(kt * 64 + row) * 512 + col * 16);
        }
    };

    wmma::fragment<wmma::accumulator, 16, 16, 16, float> accO[2][4];
    #pragma unroll
    for (int m = 0; m < 2; m++)
        #pragma unroll
        for (int n = 0; n < 4; n++) wmma::fill_fragment(accO[m][n], 0.0f);
    float lpart = 0.0f;
    const float L2E = 1.44269504f;

    loadtile(0);
    CP_COMMIT();
    for (int kt = 0; kt < PV_NT; kt++) {
        __syncthreads();
        if (kt + 1 < PV_NT) { loadtile(kt + 1); CP_COMMIT(); CP_WAIT(1); }
        else                { CP_WAIT(0); }
        __syncthreads();
        const char* Sb = smem + ((kt & 1) ? PV_S1 : PV_S0);
        const __half* Vs = (const __half*)(smem + ((kt & 1) ? PV_V1 : PV_V0));

        {   // softmax strip: row r, 16 cols at g*16; P fp16, l from rounded p
            const float4* srow = (const float4*)(Sb + r * 272 + g * 64);
            __half2* prow = (__half2*)(smem + PV_P + r * 144 + g * 32);
            const float mr = ms[r];
            #pragma unroll
            for (int j4 = 0; j4 < 4; j4++) {
                float4 s4 = srow[j4];
                float p0 = exp2f((s4.x - mr) * L2E);
                float p1 = exp2f((s4.y - mr) * L2E);
                float p2 = exp2f((s4.z - mr) * L2E);
                float p3 = exp2f((s4.w - mr) * L2E);
                __half2 h01 = __floats2half2_rn(p0, p1);
                __half2 h23 = __floats2half2_rn(p2, p3);
                float2 b01 = __half22float2(h01);
                float2 b23 = __half22float2(h23);
                lpart += (b01.x + b01.y) + (b23.x + b23.y);
                prow[j4 * 2 + 0] = h01;
                prow[j4 * 2 + 1] = h23;
            }
        }
        __syncthreads();

        {   // PV accumulate (fp16 x fp16 -> fp32)
            const __half* Ps = (const __half*)(smem + PV_P);
            wmma::fragment<wmma::matrix_a, 16, 16, 16, __half, wmma::row_major> pa[2];
            wmma::fragment<wmma::matrix_b, 16, 16, 16, __half, wmma::row_major> vb;
            #pragma unroll
            for (int kk = 0; kk < 4; kk++) {
                #pragma unroll
                for (int m = 0; m < 2; m++)
                    wmma::load_matrix_sync(pa[m], Ps + (mw2 * 32 + m * 16) * PV_PLD + kk * 16, PV_PLD);
                #pragma unroll
                for (int n = 0; n < 4; n++) {
                    wmma::load_matrix_sync(vb, Vs + (kk * 16) * PV_VLD + dv * 64 + n * 16, PV_VLD);
                    #pragma unroll
                    for (int m = 0; m < 2; m++)
                        wmma::mma_sync(accO[m][n], pa[m], vb, accO[m][n]);
                }
            }
        }
    }

    // epilogue: stage O via smem (reuses V area), scale by 1/l, write out
    Rl[r * 4 + g] = lpart;
    __syncthreads();
    float* Os = (float*)(smem + PV_V0);
    #pragma unroll
    for (int m = 0; m < 2; m++)
        #pragma unroll
        for (int n = 0; n < 4; n++)
            wmma::store_matrix_sync(Os + (mw2 * 32 + m * 16) * PV_OLD + dv * 64 + n * 16,
                                    accO[m][n], PV_OLD, wmma::mem_row_major);
    __syncthreads();
    const float linv = 1.0f / (Rl[r * 4 + 0] + Rl[r * 4 + 1] + Rl[r * 4 + 2] + Rl[r * 4 + 3]);
    float* orow = out + ((size_t)b * SEQ + q0 + r) * HID + g * 64;
    const float* srow = Os + r * PV_OLD + g * 64;
    #pragma unroll
    for (int j = 0; j < 16; j++) {
        float4 v = *reinterpret_cast<const float4*>(srow + j * 4);
        v.x *= linv; v.y *= linv; v.z *= linv; v.w *= linv;
        *reinterpret_cast<float4*>(orow + j * 4) = v;
    }
}

// ---------------------------------------------------------------------------
extern "C" void kernel_launch(void* const* d_in, const int* in_sizes, int n_in,
                              void* d_out, int out_size)
{
    const float* X  = (const float*)d_in[0];
    const float* Wq = (const float*)d_in[1];
    const float* Wk = (const float*)d_in[2];
    const float* Wv = (const float*)d_in[3];
    // d_in[4] = lengths (unused by the reference module)
    float* out = (float*)d_out;

    cudaFuncSetAttribute(s_gemm, cudaFuncAttributeMaxDynamicSharedMemorySize, SG_SMEM);
    cudaFuncSetAttribute(pv,     cudaFuncAttributeMaxDynamicSharedMemorySize, PV_SMEM);

    init_rmax<<<MTOT / 256, 256>>>();
    qkv_gemm<<<dim3(MTOT / 64, HID / 64, 3), 256>>>(X, Wq, Wk, Wv);
    s_gemm<<<dim3(SEQ / 128, SEQ / 128, BATCH), 256, SG_SMEM>>>();
    pv<<<dim3(SEQ / 64, BATCH), 256, PV_SMEM>>>(out);
}

// round 11
// speedup vs baseline: 5.1518x; 1.1236x over previous
#include <cuda_runtime.h>
#include <cuda_bf16.h>
#include <cuda_fp16.h>
#include <mma.h>
#include <cstdint>
using namespace nvcuda;

#define BATCH 4
#define SEQ   4096
#define HID   256
#define MTOT  (BATCH * SEQ)

__device__ __align__(16) __nv_bfloat16 g_Qh[MTOT * HID];
__device__ __align__(16) __nv_bfloat16 g_Ql[MTOT * HID];
__device__ __align__(16) __nv_bfloat16 g_Kh[MTOT * HID];
__device__ __align__(16) __nv_bfloat16 g_Kl[MTOT * HID];
__device__ __align__(16) __half        g_Vh[MTOT * HID];
__device__ __align__(16) float         g_S [(size_t)BATCH * SEQ * SEQ];   // 256 MB
__device__ unsigned g_rmax[MTOT];

__device__ __forceinline__ uint32_t smem_u32(const void* p) {
    uint32_t a;
    asm("{ .reg .u64 t; cvta.to.shared.u64 t, %1; cvt.u32.u64 %0, t; }" : "=r"(a) : "l"(p));
    return a;
}
__device__ __forceinline__ unsigned enc_f(float f) {
    unsigned u = __float_as_uint(f);
    return (u & 0x80000000u) ? ~u : (u | 0x80000000u);
}
__device__ __forceinline__ float dec_f(unsigned e) {
    unsigned u = (e & 0x80000000u) ? (e ^ 0x80000000u) : ~e;
    return __uint_as_float(u);
}
#define CPA(dst, src) \
    asm volatile("cp.async.cg.shared.global [%0], [%1], 16;" :: "r"(dst), "l"(src))
#define CP_COMMIT() asm volatile("cp.async.commit_group;" ::: "memory")
#define CP_WAIT(n)  asm volatile("cp.async.wait_group %0;" :: "n"(n) : "memory")

#define LDSM4(r, a) \
    asm volatile("ldmatrix.sync.aligned.m8n8.x4.shared.b16 {%0,%1,%2,%3}, [%4];" \
        : "=r"((r)[0]), "=r"((r)[1]), "=r"((r)[2]), "=r"((r)[3]) : "r"(a))

__device__ __forceinline__ void mma_bf16(float* c, const uint32_t* a, uint32_t b0, uint32_t b1) {
    asm volatile(
        "mma.sync.aligned.m16n8k16.row.col.f32.bf16.bf16.f32 "
        "{%0,%1,%2,%3}, {%4,%5,%6,%7}, {%8,%9}, {%0,%1,%2,%3};"
        : "+f"(c[0]), "+f"(c[1]), "+f"(c[2]), "+f"(c[3])
        : "r"(a[0]), "r"(a[1]), "r"(a[2]), "r"(a[3]), "r"(b0), "r"(b1));
}

// ---------------------------------------------------------------------------
// Kernel 1: fused QKV projection (fp32 GEMM), formatted outputs.
// Also zeroes g_rmax (z==0, bn==0 CTAs).
// ---------------------------------------------------------------------------
__global__ __launch_bounds__(256) void qkv_gemm(
    const float* __restrict__ X, const float* __restrict__ Wq,
    const float* __restrict__ Wk, const float* __restrict__ Wv)
{
    __shared__ float As[64][33];
    __shared__ float Bs[32][64];
    const int z = blockIdx.z;
    const float* W = (z == 0) ? Wq : (z == 1) ? Wk : Wv;
    const int bm = blockIdx.x * 64, bn = blockIdx.y * 64;
    const int t = threadIdx.x, tx = t & 15, ty = t >> 4;

    if (z == 0 && blockIdx.y == 0 && t < 64) g_rmax[bm + t] = 0u;

    float acc[4][4] = {};

    for (int k0 = 0; k0 < HID; k0 += 32) {
        #pragma unroll
        for (int e = 0; e < 2; e++) {
            int f = e * 256 + t, m = f >> 3, k4 = f & 7;
            float4 v = *reinterpret_cast<const float4*>(X + (size_t)(bm + m) * HID + k0 + k4 * 4);
            As[m][k4 * 4 + 0] = v.x; As[m][k4 * 4 + 1] = v.y;
            As[m][k4 * 4 + 2] = v.z; As[m][k4 * 4 + 3] = v.w;
        }
        #pragma unroll
        for (int e = 0; e < 2; e++) {
            int f = e * 256 + t, k = f >> 4, n4 = f & 15;
            float4 v = *reinterpret_cast<const float4*>(W + (size_t)(k0 + k) * HID + bn + n4 * 4);
            *reinterpret_cast<float4*>(&Bs[k][n4 * 4]) = v;
        }
        __syncthreads();
        #pragma unroll
        for (int kk = 0; kk < 32; kk++) {
            float a0 = As[ty * 4 + 0][kk], a1 = As[ty * 4 + 1][kk];
            float a2 = As[ty * 4 + 2][kk], a3 = As[ty * 4 + 3][kk];
            float4 bb = *reinterpret_cast<const float4*>(&Bs[kk][tx * 4]);
            acc[0][0] += a0 * bb.x; acc[0][1] += a0 * bb.y; acc[0][2] += a0 * bb.z; acc[0][3] += a0 * bb.w;
            acc[1][0] += a1 * bb.x; acc[1][1] += a1 * bb.y; acc[1][2] += a1 * bb.z; acc[1][3] += a1 * bb.w;
            acc[2][0] += a2 * bb.x; acc[2][1] += a2 * bb.y; acc[2][2] += a2 * bb.z; acc[2][3] += a2 * bb.w;
            acc[3][0] += a3 * bb.x; acc[3][1] += a3 * bb.y; acc[3][2] += a3 * bb.z; acc[3][3] += a3 * bb.w;
        }
        __syncthreads();
    }

    if (z == 2) {
        #pragma unroll
        for (int r = 0; r < 4; r++) {
            size_t base = (size_t)(bm + ty * 4 + r) * HID + bn + tx * 4;
            #pragma unroll
            for (int c = 0; c < 4; c++) g_Vh[base + c] = __float2half_rn(acc[r][c]);
        }
    } else {
        const float s = (z == 0) ? 0.0625f : 1.0f;       // fold 1/sqrt(256) into Q
        __nv_bfloat16* Gh = (z == 0) ? g_Qh : g_Kh;
        __nv_bfloat16* Gl = (z == 0) ? g_Ql : g_Kl;
        #pragma unroll
        for (int r = 0; r < 4; r++) {
            size_t base = (size_t)(bm + ty * 4 + r) * HID + bn + tx * 4;
            #pragma unroll
            for (int c = 0; c < 4; c++) {
                float v = acc[r][c] * s;
                __nv_bfloat16 h = __float2bfloat16_rn(v);
                Gh[base + c] = h;
                Gl[base + c] = __float2bfloat16_rn(v - __bfloat162float(h));
            }
        }
    }
}

// ---------------------------------------------------------------------------
// Kernel 2: S = Q K^T (bf16 x3) + per-row max.  Raw mma/ldmatrix.
// CTA 128q x 128k, BK=32 double-buffered, 256 thr (4x2 warps, 32x64/warp).
// Accumulators go straight to registers -> rowmax (shfl) -> gmem. No S smem.
// ---------------------------------------------------------------------------
#define SG_QH    0
#define SG_QL    10240
#define SG_KH    20480
#define SG_KL    30720
#define SG_STG   40960                 // bytes per stage
#define SG_SMEM  81920

__global__ __launch_bounds__(256, 2) void s_gemm()
{
    extern __shared__ __align__(1024) char smem[];
    const uint32_t sm32 = smem_u32(smem);
    const int tid = threadIdx.x;
    const int w = tid >> 5;
    const int lane = tid & 31;
    const int mw = w >> 1, dw = w & 1;   // 4 row-warps (32 rows) x 2 col-warps (64 cols)
    const int b = blockIdx.z;
    const int q0 = blockIdx.y * 128, k0 = blockIdx.x * 128;

    const char* QhG = (const char*)(g_Qh + (size_t)(b * SEQ + q0) * HID);
    const char* QlG = (const char*)(g_Ql + (size_t)(b * SEQ + q0) * HID);
    const char* KhG = (const char*)(g_Kh + (size_t)(b * SEQ + k0) * HID);
    const char* KlG = (const char*)(g_Kl + (size_t)(b * SEQ + k0) * HID);

    auto loadchunk = [&](int c) {            // 128 rows x 64 B per matrix
        uint32_t base = sm32 + (c & 1) * SG_STG;
        #pragma unroll
        for (int e = 0; e < 2; e++) {
            int idx = e * 256 + tid;
            int row = idx >> 2, col = idx & 3;
            uint32_t so = row * 80 + col * 16;
            size_t   go = (size_t)row * 512 + c * 64 + col * 16;
            CPA(base + SG_QH + so, QhG + go);
            CPA(base + SG_QL + so, QlG + go);
            CPA(base + SG_KH + so, KhG + go);
            CPA(base + SG_KL + so, KlG + go);
        }
    };

    float c[2][8][4];
    #pragma unroll
    for (int m = 0; m < 2; m++)
        #pragma unroll
        for (int n = 0; n < 8; n++)
            #pragma unroll
            for (int j = 0; j < 4; j++) c[m][n][j] = 0.0f;

    // ldmatrix lane-address components (80 B row stride layout)
    const uint32_t a_roff = (uint32_t)((lane & 7) + ((lane & 8) ? 8 : 0)) * 80
                          + ((lane & 16) ? 16 : 0);
    const uint32_t b_roff = (uint32_t)((lane & 7) + ((lane & 16) ? 8 : 0)) * 80
                          + ((lane & 8) ? 16 : 0);

    loadchunk(0);
    CP_COMMIT();
    for (int ch = 0; ch < 8; ch++) {
        __syncthreads();
        if (ch + 1 < 8) { loadchunk(ch + 1); CP_COMMIT(); CP_WAIT(1); }
        else            { CP_WAIT(0); }
        __syncthreads();
        const uint32_t base = sm32 + (ch & 1) * SG_STG;
        #pragma unroll
        for (int kk = 0; kk < 2; kk++) {
            uint32_t ah[2][4], al[2][4];
            #pragma unroll
            for (int m = 0; m < 2; m++) {
                uint32_t arow = (uint32_t)(mw * 32 + m * 16) * 80 + kk * 32;
                LDSM4(ah[m], base + SG_QH + arow + a_roff);
                LDSM4(al[m], base + SG_QL + arow + a_roff);
            }
            uint32_t bh[8][2], bl[8][2];
            #pragma unroll
            for (int nn = 0; nn < 4; nn++) {
                uint32_t brow = (uint32_t)(dw * 64 + nn * 16) * 80 + kk * 32;
                uint32_t r4[4];
                LDSM4(r4, base + SG_KH + brow + b_roff);
                bh[nn * 2][0] = r4[0]; bh[nn * 2][1] = r4[1];
                bh[nn * 2 + 1][0] = r4[2]; bh[nn * 2 + 1][1] = r4[3];
                LDSM4(r4, base + SG_KL + brow + b_roff);
                bl[nn * 2][0] = r4[0]; bl[nn * 2][1] = r4[1];
                bl[nn * 2 + 1][0] = r4[2]; bl[nn * 2 + 1][1] = r4[3];
            }
            #pragma unroll
            for (int m = 0; m < 2; m++)
                #pragma unroll
                for (int n = 0; n < 8; n++) {
                    mma_bf16(c[m][n], ah[m], bh[n][0], bh[n][1]);
                    mma_bf16(c[m][n], ah[m], bl[n][0], bl[n][1]);
                    mma_bf16(c[m][n], al[m], bh[n][0], bh[n][1]);
                }
        }
    }

    // ---- epilogue: rowmax from registers + direct S stores ----
    const int qr = lane >> 2;            // row within 16-row frag
    const int cg = lane & 3;             // column group
    #pragma unroll
    for (int m = 0; m < 2; m++) {
        float mx0 = c[m][0][0], mx1 = c[m][0][2];
        #pragma unroll
        for (int n = 0; n < 8; n++) {
            mx0 = fmaxf(mx0, fmaxf(c[m][n][0], c[m][n][1]));
            mx1 = fmaxf(mx1, fmaxf(c[m][n][2], c[m][n][3]));
        }
        mx0 = fmaxf(mx0, __shfl_xor_sync(0xFFFFFFFF, mx0, 1));
        mx0 = fmaxf(mx0, __shfl_xor_sync(0xFFFFFFFF, mx0, 2));
        mx1 = fmaxf(mx1, __shfl_xor_sync(0xFFFFFFFF, mx1, 1));
        mx1 = fmaxf(mx1, __shfl_xor_sync(0xFFFFFFFF, mx1, 2));
        if (cg == 0) {
            atomicMax(&g_rmax[b * SEQ + q0 + mw * 32 + m * 16 + qr], enc_f(mx0));
            atomicMax(&g_rmax[b * SEQ + q0 + mw * 32 + m * 16 + qr + 8], enc_f(mx1));
        }
        float* r0 = g_S + ((size_t)b * SEQ + q0 + mw * 32 + m * 16 + qr) * SEQ + k0 + dw * 64;
        float* r1 = r0 + (size_t)8 * SEQ;
        #pragma unroll
        for (int n = 0; n < 8; n++) {
            *reinterpret_cast<float2*>(r0 + n * 8 + cg * 2) = make_float2(c[m][n][0], c[m][n][1]);
            *reinterpret_cast<float2*>(r1 + n * 8 + cg * 2) = make_float2(c[m][n][2], c[m][n][3]);
        }
    }
}

// ---------------------------------------------------------------------------
// Kernel 3: O = softmax(S) V, fp16 HMMA.  64 q rows/CTA, KT=64 key tiles.
// grid (64, 4), 256 thr, 2 CTAs/SM.  Warp tile 32x64 (2x4 warps).
// ---------------------------------------------------------------------------
#define PV_SLD  68                    // floats (272 B/row)
#define PV_S0   0
#define PV_S1   17408
#define PV_VLD  264                   // halves (528 B/row)
#define PV_V0   34816
#define PV_V1   68608
#define PV_P    102400                // halves, ld 72 (144 B/row)
#define PV_PLD  72
#define PV_MS   111616
#define PV_RL   111872
#define PV_SMEM 112896
#define PV_OLD  264                   // f32 staging ld
#define PV_NT   (SEQ / 64)

__global__ __launch_bounds__(256, 2) void pv(float* __restrict__ out)
{
    extern __shared__ __align__(1024) char smem[];
    const uint32_t sm32 = smem_u32(smem);
    const int tid = threadIdx.x;
    const int w = tid >> 5;
    const int mw2 = w >> 2, dv = w & 3;
    const int r = tid >> 2, g = tid & 3;
    const int b = blockIdx.y;
    const int q0 = blockIdx.x * 64;

    const char* SG = (const char*)(g_S + ((size_t)b * SEQ + q0) * SEQ);
    const char* VG = (const char*)(g_Vh + (size_t)b * SEQ * HID);
    float* ms = (float*)(smem + PV_MS);
    float* Rl = (float*)(smem + PV_RL);

    if (tid < 64) ms[tid] = dec_f(g_rmax[b * SEQ + q0 + tid]);

    auto loadtile = [&](int kt) {
        uint32_t sb = sm32 + ((kt & 1) ? PV_S1 : PV_S0);
        uint32_t vb = sm32 + ((kt & 1) ? PV_V1 : PV_V0);
        #pragma unroll
        for (int e = 0; e < 4; e++) {          // S: 64 rows x 256 B
            int idx = e * 256 + tid, row = idx >> 4, col = idx & 15;
            CPA(sb + row * 272 + col * 16,
                SG + (size_t)row * (SEQ * 4) + (size_t)kt * 256 + col * 16);
        }
        #pragma unroll
        for (int e = 0; e < 8; e++) {          // V: 64 rows x 512 B (fp16)
            int idx = e * 256 + tid, row = idx >> 5, col = idx & 31;
            CPA(vb + row * 528 + col * 16,
                VG + (size_t)(kt * 64 + row) * 512 + col * 16);
        }
    };

    wmma::fragment<wmma::accumulator, 16, 16, 16, float> accO[2][4];
    #pragma unroll
    for (int m = 0; m < 2; m++)
        #pragma unroll
        for (int n = 0; n < 4; n++) wmma::fill_fragment(accO[m][n], 0.0f);
    float lpart = 0.0f;
    const float L2E = 1.44269504f;

    loadtile(0);
    CP_COMMIT();
    __syncthreads();                       // ms[] visible
    const float mr = ms[r];
    for (int kt = 0; kt < PV_NT; kt++) {
        __syncthreads();
        if (kt + 1 < PV_NT) { loadtile(kt + 1); CP_COMMIT(); CP_WAIT(1); }
        else                { CP_WAIT(0); }
        __syncthreads();
        const char* Sb = smem + ((kt & 1) ? PV_S1 : PV_S0);
        const __half* Vs = (const __half*)(smem + ((kt & 1) ? PV_V1 : PV_V0));

        {   // softmax strip: row r, 16 cols at g*16; P fp16, l from rounded p
            const float4* srow = (const float4*)(Sb + r * 272 + g * 64);
            __half2* prow = (__half2*)(smem + PV_P + r * 144 + g * 32);
            #pragma unroll
            for (int j4 = 0; j4 < 4; j4++) {
                float4 s4 = srow[j4];
                float p0 = exp2f((s4.x - mr) * L2E);
                float p1 = exp2f((s4.y - mr) * L2E);
                float p2 = exp2f((s4.z - mr) * L2E);
                float p3 = exp2f((s4.w - mr) * L2E);
                __half2 h01 = __floats2half2_rn(p0, p1);
                __half2 h23 = __floats2half2_rn(p2, p3);
                float2 b01 = __half22float2(h01);
                float2 b23 = __half22float2(h23);
                lpart += (b01.x + b01.y) + (b23.x + b23.y);
                prow[j4 * 2 + 0] = h01;
                prow[j4 * 2 + 1] = h23;
            }
        }
        __syncthreads();

        {   // PV accumulate (fp16 x fp16 -> fp32)
            const __half* Ps = (const __half*)(smem + PV_P);
            wmma::fragment<wmma::matrix_a, 16, 16, 16, __half, wmma::row_major> pa[2];
            wmma::fragment<wmma::matrix_b, 16, 16, 16, __half, wmma::row_major> vb;
            #pragma unroll
            for (int kk = 0; kk < 4; kk++) {
                #pragma unroll
                for (int m = 0; m < 2; m++)
                    wmma::load_matrix_sync(pa[m], Ps + (mw2 * 32 + m * 16) * PV_PLD + kk * 16, PV_PLD);
                #pragma unroll
                for (int n = 0; n < 4; n++) {
                    wmma::load_matrix_sync(vb, Vs + (kk * 16) * PV_VLD + dv * 64 + n * 16, PV_VLD);
                    #pragma unroll
                    for (int m = 0; m < 2; m++)
                        wmma::mma_sync(accO[m][n], pa[m], vb, accO[m][n]);
                }
            }
        }
    }

    // epilogue: stage O via smem (reuses V area), scale by 1/l, write out
    Rl[r * 4 + g] = lpart;
    __syncthreads();
    float* Os = (float*)(smem + PV_V0);
    #pragma unroll
    for (int m = 0; m < 2; m++)
        #pragma unroll
        for (int n = 0; n < 4; n++)
            wmma::store_matrix_sync(Os + (mw2 * 32 + m * 16) * PV_OLD + dv * 64 + n * 16,
                                    accO[m][n], PV_OLD, wmma::mem_row_major);
    __syncthreads();
    const float linv = 1.0f / (Rl[r * 4 + 0] + Rl[r * 4 + 1] + Rl[r * 4 + 2] + Rl[r * 4 + 3]);
    float* orow = out + ((size_t)b * SEQ + q0 + r) * HID + g * 64;
    const float* srow = Os + r * PV_OLD + g * 64;
    #pragma unroll
    for (int j = 0; j < 16; j++) {
        float4 v = *reinterpret_cast<const float4*>(srow + j * 4);
        v.x *= linv; v.y *= linv; v.z *= linv; v.w *= linv;
        *reinterpret_cast<float4*>(orow + j * 4) = v;
    }
}

// ---------------------------------------------------------------------------
extern "C" void kernel_launch(void* const* d_in, const int* in_sizes, int n_in,
                              void* d_out, int out_size)
{
    const float* X  = (const float*)d_in[0];
    const float* Wq = (const float*)d_in[1];
    const float* Wk = (const float*)d_in[2];
    const float* Wv = (const float*)d_in[3];
    // d_in[4] = lengths (unused by the reference module)
    float* out = (float*)d_out;

    cudaFuncSetAttribute(s_gemm, cudaFuncAttributeMaxDynamicSharedMemorySize, SG_SMEM);
    cudaFuncSetAttribute(pv,     cudaFuncAttributeMaxDynamicSharedMemorySize, PV_SMEM);

    qkv_gemm<<<dim3(MTOT / 64, HID / 64, 3), 256>>>(X, Wq, Wk, Wv);
    s_gemm<<<dim3(SEQ / 128, SEQ / 128, BATCH), 256, SG_SMEM>>>();
    pv<<<dim3(SEQ / 64, BATCH), 256, PV_SMEM>>>(out);
}

// round 12
// speedup vs baseline: 5.9848x; 1.1617x over previous
#include <cuda_runtime.h>
#include <cuda_bf16.h>
#include <cuda_fp16.h>
#include <mma.h>
#include <cstdint>
using namespace nvcuda;

#define BATCH 4
#define SEQ   4096
#define HID   256
#define MTOT  (BATCH * SEQ)

__device__ __align__(16) __nv_bfloat16 g_Qh[MTOT * HID];
__device__ __align__(16) __nv_bfloat16 g_Ql[MTOT * HID];
__device__ __align__(16) __nv_bfloat16 g_Kh[MTOT * HID];
__device__ __align__(16) __nv_bfloat16 g_Kl[MTOT * HID];
__device__ __align__(16) __half        g_Vh[MTOT * HID];
__device__ __align__(16) float         g_S [(size_t)BATCH * SEQ * SEQ];   // 256 MB
__device__ __align__(16) __nv_bfloat16 g_Xh[MTOT * HID];
__device__ __align__(16) __nv_bfloat16 g_Xl[MTOT * HID];
__device__ __align__(16) __nv_bfloat16 g_Wth[3 * HID * HID];   // [z][n][k]
__device__ __align__(16) __nv_bfloat16 g_Wtl[3 * HID * HID];
__device__ unsigned g_rmax[MTOT];

__device__ __forceinline__ uint32_t smem_u32(const void* p) {
    uint32_t a;
    asm("{ .reg .u64 t; cvta.to.shared.u64 t, %1; cvt.u32.u64 %0, t; }" : "=r"(a) : "l"(p));
    return a;
}
__device__ __forceinline__ unsigned enc_f(float f) {
    unsigned u = __float_as_uint(f);
    return (u & 0x80000000u) ? ~u : (u | 0x80000000u);
}
__device__ __forceinline__ float dec_f(unsigned e) {
    unsigned u = (e & 0x80000000u) ? (e ^ 0x80000000u) : ~e;
    return __uint_as_float(u);
}
#define CPA(dst, src) \
    asm volatile("cp.async.cg.shared.global [%0], [%1], 16;" :: "r"(dst), "l"(src))
#define CP_COMMIT() asm volatile("cp.async.commit_group;" ::: "memory")
#define CP_WAIT(n)  asm volatile("cp.async.wait_group %0;" :: "n"(n) : "memory")

#define LDSM4(r, a) \
    asm volatile("ldmatrix.sync.aligned.m8n8.x4.shared.b16 {%0,%1,%2,%3}, [%4];" \
        : "=r"((r)[0]), "=r"((r)[1]), "=r"((r)[2]), "=r"((r)[3]) : "r"(a))

__device__ __forceinline__ void mma_bf16(float* c, const uint32_t* a, uint32_t b0, uint32_t b1) {
    asm volatile(
        "mma.sync.aligned.m16n8k16.row.col.f32.bf16.bf16.f32 "
        "{%0,%1,%2,%3}, {%4,%5,%6,%7}, {%8,%9}, {%0,%1,%2,%3};"
        : "+f"(c[0]), "+f"(c[1]), "+f"(c[2]), "+f"(c[3])
        : "r"(a[0]), "r"(a[1]), "r"(a[2]), "r"(a[3]), "r"(b0), "r"(b1));
}

// ---------------------------------------------------------------------------
// prep_x: split X -> bf16 hi/lo; zero g_rmax.
// ---------------------------------------------------------------------------
__global__ __launch_bounds__(256) void prep_x(const float* __restrict__ X)
{
    int idx = blockIdx.x * 256 + threadIdx.x;          // 1 float4 per thread
    float4 v = *reinterpret_cast<const float4*>(X + (size_t)idx * 4);
    __nv_bfloat16 h0 = __float2bfloat16_rn(v.x);
    __nv_bfloat16 h1 = __float2bfloat16_rn(v.y);
    __nv_bfloat16 h2 = __float2bfloat16_rn(v.z);
    __nv_bfloat16 h3 = __float2bfloat16_rn(v.w);
    __nv_bfloat162* H = reinterpret_cast<__nv_bfloat162*>(g_Xh + (size_t)idx * 4);
    __nv_bfloat162* L = reinterpret_cast<__nv_bfloat162*>(g_Xl + (size_t)idx * 4);
    H[0] = {h0, h1}; H[1] = {h2, h3};
    L[0] = {__float2bfloat16_rn(v.x - __bfloat162float(h0)),
            __float2bfloat16_rn(v.y - __bfloat162float(h1))};
    L[1] = {__float2bfloat16_rn(v.z - __bfloat162float(h2)),
            __float2bfloat16_rn(v.w - __bfloat162float(h3))};
    if (idx < MTOT) g_rmax[idx] = 0u;
}

// ---------------------------------------------------------------------------
// prep_w: split + transpose W -> g_Wth/g_Wtl [z][n][k].
// grid (HID, 3), 256 thr: block = row k of W_z; thread = n.
// ---------------------------------------------------------------------------
__global__ __launch_bounds__(256) void prep_w(
    const float* __restrict__ Wq, const float* __restrict__ Wk,
    const float* __restrict__ Wv)
{
    const int z = blockIdx.y, k = blockIdx.x, n = threadIdx.x;
    const float* W = (z == 0) ? Wq : (z == 1) ? Wk : Wv;
    float v = W[k * HID + n];
    __nv_bfloat16 h = __float2bfloat16_rn(v);
    g_Wth[(size_t)z * HID * HID + (size_t)n * HID + k] = h;
    g_Wtl[(size_t)z * HID * HID + (size_t)n * HID + k] =
        __float2bfloat16_rn(v - __bfloat162float(h));
}

// ---------------------------------------------------------------------------
// qkv_tc: bf16x3 tensor-core QKV projection.
// C[128 rows x 128 cols] per CTA; grid (128, 6) = (m-tile, z*2 + n-half).
// Epilogue splits Q/K to bf16 hi/lo or rounds V to fp16, from registers.
// ---------------------------------------------------------------------------
#define QT_AH    0
#define QT_AL    10240
#define QT_BH    20480
#define QT_BL    30720
#define QT_STG   40960
#define QT_SMEM  81920

__global__ __launch_bounds__(256, 2) void qkv_tc()
{
    extern __shared__ __align__(1024) char smem[];
    const uint32_t sm32 = smem_u32(smem);
    const int tid = threadIdx.x;
    const int w = tid >> 5;
    const int lane = tid & 31;
    const int mw = w >> 1, dw = w & 1;
    const int m0 = blockIdx.x * 128;
    const int z = blockIdx.y >> 1;
    const int n0 = (blockIdx.y & 1) * 128;

    const char* AhG = (const char*)(g_Xh + (size_t)m0 * HID);
    const char* AlG = (const char*)(g_Xl + (size_t)m0 * HID);
    const char* BhG = (const char*)(g_Wth + (size_t)z * HID * HID + (size_t)n0 * HID);
    const char* BlG = (const char*)(g_Wtl + (size_t)z * HID * HID + (size_t)n0 * HID);

    auto loadchunk = [&](int c) {
        uint32_t base = sm32 + (c & 1) * QT_STG;
        #pragma unroll
        for (int e = 0; e < 2; e++) {
            int idx = e * 256 + tid;
            int row = idx >> 2, col = idx & 3;
            uint32_t so = row * 80 + col * 16;
            size_t   go = (size_t)row * 512 + c * 64 + col * 16;
            CPA(base + QT_AH + so, AhG + go);
            CPA(base + QT_AL + so, AlG + go);
            CPA(base + QT_BH + so, BhG + go);
            CPA(base + QT_BL + so, BlG + go);
        }
    };

    float c[2][8][4];
    #pragma unroll
    for (int m = 0; m < 2; m++)
        #pragma unroll
        for (int n = 0; n < 8; n++)
            #pragma unroll
            for (int j = 0; j < 4; j++) c[m][n][j] = 0.0f;

    const uint32_t a_roff = (uint32_t)((lane & 7) + ((lane & 8) ? 8 : 0)) * 80
                          + ((lane & 16) ? 16 : 0);
    const uint32_t b_roff = (uint32_t)((lane & 7) + ((lane & 16) ? 8 : 0)) * 80
                          + ((lane & 8) ? 16 : 0);

    loadchunk(0);
    CP_COMMIT();
    for (int ch = 0; ch < 8; ch++) {
        __syncthreads();
        if (ch + 1 < 8) { loadchunk(ch + 1); CP_COMMIT(); CP_WAIT(1); }
        else            { CP_WAIT(0); }
        __syncthreads();
        const uint32_t base = sm32 + (ch & 1) * QT_STG;
        #pragma unroll
        for (int kk = 0; kk < 2; kk++) {
            uint32_t ah[2][4], al[2][4];
            #pragma unroll
            for (int m = 0; m < 2; m++) {
                uint32_t arow = (uint32_t)(mw * 32 + m * 16) * 80 + kk * 32;
                LDSM4(ah[m], base + QT_AH + arow + a_roff);
                LDSM4(al[m], base + QT_AL + arow + a_roff);
            }
            uint32_t bh[8][2], bl[8][2];
            #pragma unroll
            for (int nn = 0; nn < 4; nn++) {
                uint32_t brow = (uint32_t)(dw * 64 + nn * 16) * 80 + kk * 32;
                uint32_t r4[4];
                LDSM4(r4, base + QT_BH + brow + b_roff);
                bh[nn * 2][0] = r4[0]; bh[nn * 2][1] = r4[1];
                bh[nn * 2 + 1][0] = r4[2]; bh[nn * 2 + 1][1] = r4[3];
                LDSM4(r4, base + QT_BL + brow + b_roff);
                bl[nn * 2][0] = r4[0]; bl[nn * 2][1] = r4[1];
                bl[nn * 2 + 1][0] = r4[2]; bl[nn * 2 + 1][1] = r4[3];
            }
            #pragma unroll
            for (int m = 0; m < 2; m++)
                #pragma unroll
                for (int n = 0; n < 8; n++) {
                    mma_bf16(c[m][n], ah[m], bh[n][0], bh[n][1]);
                    mma_bf16(c[m][n], ah[m], bl[n][0], bl[n][1]);
                    mma_bf16(c[m][n], al[m], bh[n][0], bh[n][1]);
                }
        }
    }

    // ---- epilogue: split/round from registers ----
    const int qr = lane >> 2;
    const int cg = lane & 3;
    const float s = (z == 0) ? 0.0625f : 1.0f;
    #pragma unroll
    for (int m = 0; m < 2; m++) {
        int row0 = m0 + mw * 32 + m * 16 + qr;
        int colb = n0 + dw * 64 + cg * 2;
        if (z == 2) {
            #pragma unroll
            for (int rr = 0; rr < 2; rr++) {
                __half* Vr = g_Vh + (size_t)(row0 + rr * 8) * HID;
                #pragma unroll
                for (int n = 0; n < 8; n++)
                    *reinterpret_cast<__half2*>(Vr + colb + n * 8) =
                        __floats2half2_rn(c[m][n][rr * 2], c[m][n][rr * 2 + 1]);
            }
        } else {
            __nv_bfloat16* Gh = (z == 0) ? g_Qh : g_Kh;
            __nv_bfloat16* Gl = (z == 0) ? g_Ql : g_Kl;
            #pragma unroll
            for (int rr = 0; rr < 2; rr++) {
                size_t rb = (size_t)(row0 + rr * 8) * HID;
                #pragma unroll
                for (int n = 0; n < 8; n++) {
                    float v0 = c[m][n][rr * 2] * s, v1 = c[m][n][rr * 2 + 1] * s;
                    __nv_bfloat16 h0 = __float2bfloat16_rn(v0);
                    __nv_bfloat16 h1 = __float2bfloat16_rn(v1);
                    *reinterpret_cast<__nv_bfloat162*>(Gh + rb + colb + n * 8) = {h0, h1};
                    *reinterpret_cast<__nv_bfloat162*>(Gl + rb + colb + n * 8) =
                        {__float2bfloat16_rn(v0 - __bfloat162float(h0)),
                         __float2bfloat16_rn(v1 - __bfloat162float(h1))};
                }
            }
        }
    }
}

// ---------------------------------------------------------------------------
// Kernel 2: S = Q K^T (bf16 x3) + per-row max.  Raw mma/ldmatrix.
// ---------------------------------------------------------------------------
#define SG_QH    0
#define SG_QL    10240
#define SG_KH    20480
#define SG_KL    30720
#define SG_STG   40960
#define SG_SMEM  81920

__global__ __launch_bounds__(256, 2) void s_gemm()
{
    extern __shared__ __align__(1024) char smem[];
    const uint32_t sm32 = smem_u32(smem);
    const int tid = threadIdx.x;
    const int w = tid >> 5;
    const int lane = tid & 31;
    const int mw = w >> 1, dw = w & 1;
    const int b = blockIdx.z;
    const int q0 = blockIdx.y * 128, k0 = blockIdx.x * 128;

    const char* QhG = (const char*)(g_Qh + (size_t)(b * SEQ + q0) * HID);
    const char* QlG = (const char*)(g_Ql + (size_t)(b * SEQ + q0) * HID);
    const char* KhG = (const char*)(g_Kh + (size_t)(b * SEQ + k0) * HID);
    const char* KlG = (const char*)(g_Kl + (size_t)(b * SEQ + k0) * HID);

    auto loadchunk = [&](int c) {
        uint32_t base = sm32 + (c & 1) * SG_STG;
        #pragma unroll
        for (int e = 0; e < 2; e++) {
            int idx = e * 256 + tid;
            int row = idx >> 2, col = idx & 3;
            uint32_t so = row * 80 + col * 16;
            size_t   go = (size_t)row * 512 + c * 64 + col * 16;
            CPA(base + SG_QH + so, QhG + go);
            CPA(base + SG_QL + so, QlG + go);
            CPA(base + SG_KH + so, KhG + go);
            CPA(base + SG_KL + so, KlG + go);
        }
    };

    float c[2][8][4];
    #pragma unroll
    for (int m = 0; m < 2; m++)
        #pragma unroll
        for (int n = 0; n < 8; n++)
            #pragma unroll
            for (int j = 0; j < 4; j++) c[m][n][j] = 0.0f;

    const uint32_t a_roff = (uint32_t)((lane & 7) + ((lane & 8) ? 8 : 0)) * 80
                          + ((lane & 16) ? 16 : 0);
    const uint32_t b_roff = (uint32_t)((lane & 7) + ((lane & 16) ? 8 : 0)) * 80
                          + ((lane & 8) ? 16 : 0);

    loadchunk(0);
    CP_COMMIT();
    for (int ch = 0; ch < 8; ch++) {
        __syncthreads();
        if (ch + 1 < 8) { loadchunk(ch + 1); CP_COMMIT(); CP_WAIT(1); }
        else            { CP_WAIT(0); }
        __syncthreads();
        const uint32_t base = sm32 + (ch & 1) * SG_STG;
        #pragma unroll
        for (int kk = 0; kk < 2; kk++) {
            uint32_t ah[2][4], al[2][4];
            #pragma unroll
            for (int m = 0; m < 2; m++) {
                uint32_t arow = (uint32_t)(mw * 32 + m * 16) * 80 + kk * 32;
                LDSM4(ah[m], base + SG_QH + arow + a_roff);
                LDSM4(al[m], base + SG_QL + arow + a_roff);
            }
            uint32_t bh[8][2], bl[8][2];
            #pragma unroll
            for (int nn = 0; nn < 4; nn++) {
                uint32_t brow = (uint32_t)(dw * 64 + nn * 16) * 80 + kk * 32;
                uint32_t r4[4];
                LDSM4(r4, base + SG_KH + brow + b_roff);
                bh[nn * 2][0] = r4[0]; bh[nn * 2][1] = r4[1];
                bh[nn * 2 + 1][0] = r4[2]; bh[nn * 2 + 1][1] = r4[3];
                LDSM4(r4, base + SG_KL + brow + b_roff);
                bl[nn * 2][0] = r4[0]; bl[nn * 2][1] = r4[1];
                bl[nn * 2 + 1][0] = r4[2]; bl[nn * 2 + 1][1] = r4[3];
            }
            #pragma unroll
            for (int m = 0; m < 2; m++)
                #pragma unroll
                for (int n = 0; n < 8; n++) {
                    mma_bf16(c[m][n], ah[m], bh[n][0], bh[n][1]);
                    mma_bf16(c[m][n], ah[m], bl[n][0], bl[n][1]);
                    mma_bf16(c[m][n], al[m], bh[n][0], bh[n][1]);
                }
        }
    }

    const int qr = lane >> 2;
    const int cg = lane & 3;
    #pragma unroll
    for (int m = 0; m < 2; m++) {
        float mx0 = c[m][0][0], mx1 = c[m][0][2];
        #pragma unroll
        for (int n = 0; n < 8; n++) {
            mx0 = fmaxf(mx0, fmaxf(c[m][n][0], c[m][n][1]));
            mx1 = fmaxf(mx1, fmaxf(c[m][n][2], c[m][n][3]));
        }
        mx0 = fmaxf(mx0, __shfl_xor_sync(0xFFFFFFFF, mx0, 1));
        mx0 = fmaxf(mx0, __shfl_xor_sync(0xFFFFFFFF, mx0, 2));
        mx1 = fmaxf(mx1, __shfl_xor_sync(0xFFFFFFFF, mx1, 1));
        mx1 = fmaxf(mx1, __shfl_xor_sync(0xFFFFFFFF, mx1, 2));
        if (cg == 0) {
            atomicMax(&g_rmax[b * SEQ + q0 + mw * 32 + m * 16 + qr], enc_f(mx0));
            atomicMax(&g_rmax[b * SEQ + q0 + mw * 32 + m * 16 + qr + 8], enc_f(mx1));
        }
        float* r0 = g_S + ((size_t)b * SEQ + q0 + mw * 32 + m * 16 + qr) * SEQ + k0 + dw * 64;
        float* r1 = r0 + (size_t)8 * SEQ;
        #pragma unroll
        for (int n = 0; n < 8; n++) {
            *reinterpret_cast<float2*>(r0 + n * 8 + cg * 2) = make_float2(c[m][n][0], c[m][n][1]);
            *reinterpret_cast<float2*>(r1 + n * 8 + cg * 2) = make_float2(c[m][n][2], c[m][n][3]);
        }
    }
}

// ---------------------------------------------------------------------------
// Kernel 3: O = softmax(S) V, fp16 HMMA.  64 q rows/CTA, KT=64 key tiles.
// ---------------------------------------------------------------------------
#define PV_S0   0
#define PV_S1   17408
#define PV_VLD  264
#define PV_V0   34816
#define PV_V1   68608
#define PV_P    102400
#define PV_PLD  72
#define PV_MS   111616
#define PV_RL   111872
#define PV_SMEM 112896
#define PV_OLD  264
#define PV_NT   (SEQ / 64)

__global__ __launch_bounds__(256, 2) void pv(float* __restrict__ out)
{
    extern __shared__ __align__(1024) char smem[];
    const uint32_t sm32 = smem_u32(smem);
    const int tid = threadIdx.x;
    const int w = tid >> 5;
    const int mw2 = w >> 2, dv = w & 3;
    const int r = tid >> 2, g = tid & 3;
    const int b = blockIdx.y;
    const int q0 = blockIdx.x * 64;

    const char* SG = (const char*)(g_S + ((size_t)b * SEQ + q0) * SEQ);
    const char* VG = (const char*)(g_Vh + (size_t)b * SEQ * HID);
    float* ms = (float*)(smem + PV_MS);
    float* Rl = (float*)(smem + PV_RL);

    if (tid < 64) ms[tid] = dec_f(g_rmax[b * SEQ + q0 + tid]);

    auto loadtile = [&](int kt) {
        uint32_t sb = sm32 + ((kt & 1) ? PV_S1 : PV_S0);
        uint32_t vb = sm32 + ((kt & 1) ? PV_V1 : PV_V0);
        #pragma unroll
        for (int e = 0; e < 4; e++) {
            int idx = e * 256 + tid, row = idx >> 4, col = idx & 15;
            CPA(sb + row * 272 + col * 16,
                SG + (size_t)row * (SEQ * 4) + (size_t)kt * 256 + col * 16);
        }
        #pragma unroll
        for (int e = 0; e < 8; e++) {
            int idx = e * 256 + tid, row = idx >> 5, col = idx & 31;
            CPA(vb + row * 528 + col * 16,
                VG + (size_t)(kt * 64 + row) * 512 + col * 16);
        }
    };

    wmma::fragment<wmma::accumulator, 16, 16, 16, float> accO[2][4];
    #pragma unroll
    for (int m = 0; m < 2; m++)
        #pragma unroll
        for (int n = 0; n < 4; n++) wmma::fill_fragment(accO[m][n], 0.0f);
    float lpart = 0.0f;
    const float L2E = 1.44269504f;

    loadtile(0);
    CP_COMMIT();
    __syncthreads();
    const float mr = ms[r];
    for (int kt = 0; kt < PV_NT; kt++) {
        __syncthreads();
        if (kt + 1 < PV_NT) { loadtile(kt + 1); CP_COMMIT(); CP_WAIT(1); }
        else                { CP_WAIT(0); }
        __syncthreads();
        const char* Sb = smem + ((kt & 1) ? PV_S1 : PV_S0);
        const __half* Vs = (const __half*)(smem + ((kt & 1) ? PV_V1 : PV_V0));

        {
            const float4* srow = (const float4*)(Sb + r * 272 + g * 64);
            __half2* prow = (__half2*)(smem + PV_P + r * 144 + g * 32);
            #pragma unroll
            for (int j4 = 0; j4 < 4; j4++) {
                float4 s4 = srow[j4];
                float p0 = exp2f((s4.x - mr) * L2E);
                float p1 = exp2f((s4.y - mr) * L2E);
                float p2 = exp2f((s4.z - mr) * L2E);
                float p3 = exp2f((s4.w - mr) * L2E);
                __half2 h01 = __floats2half2_rn(p0, p1);
                __half2 h23 = __floats2half2_rn(p2, p3);
                float2 b01 = __half22float2(h01);
                float2 b23 = __half22float2(h23);
                lpart += (b01.x + b01.y) + (b23.x + b23.y);
                prow[j4 * 2 + 0] = h01;
                prow[j4 * 2 + 1] = h23;
            }
        }
        __syncthreads();

        {
            const __half* Ps = (const __half*)(smem + PV_P);
            wmma::fragment<wmma::matrix_a, 16, 16, 16, __half, wmma::row_major> pa[2];
            wmma::fragment<wmma::matrix_b, 16, 16, 16, __half, wmma::row_major> vb;
            #pragma unroll
            for (int kk = 0; kk < 4; kk++) {
                #pragma unroll
                for (int m = 0; m < 2; m++)
                    wmma::load_matrix_sync(pa[m], Ps + (mw2 * 32 + m * 16) * PV_PLD + kk * 16, PV_PLD);
                #pragma unroll
                for (int n = 0; n < 4; n++) {
                    wmma::load_matrix_sync(vb, Vs + (kk * 16) * PV_VLD + dv * 64 + n * 16, PV_VLD);
                    #pragma unroll
                    for (int m = 0; m < 2; m++)
                        wmma::mma_sync(accO[m][n], pa[m], vb, accO[m][n]);
                }
            }
        }
    }

    Rl[r * 4 + g] = lpart;
    __syncthreads();
    float* Os = (float*)(smem + PV_V0);
    #pragma unroll
    for (int m = 0; m < 2; m++)
        #pragma unroll
        for (int n = 0; n < 4; n++)
            wmma::store_matrix_sync(Os + (mw2 * 32 + m * 16) * PV_OLD + dv * 64 + n * 16,
                                    accO[m][n], PV_OLD, wmma::mem_row_major);
    __syncthreads();
    const float linv = 1.0f / (Rl[r * 4 + 0] + Rl[r * 4 + 1] + Rl[r * 4 + 2] + Rl[r * 4 + 3]);
    float* orow = out + ((size_t)b * SEQ + q0 + r) * HID + g * 64;
    const float* srow = Os + r * PV_OLD + g * 64;
    #pragma unroll
    for (int j = 0; j < 16; j++) {
        float4 v = *reinterpret_cast<const float4*>(srow + j * 4);
        v.x *= linv; v.y *= linv; v.z *= linv; v.w *= linv;
        *reinterpret_cast<float4*>(orow + j * 4) = v;
    }
}

// ---------------------------------------------------------------------------
extern "C" void kernel_launch(void* const* d_in, const int* in_sizes, int n_in,
                              void* d_out, int out_size)
{
    const float* X  = (const float*)d_in[0];
    const float* Wq = (const float*)d_in[1];
    const float* Wk = (const float*)d_in[2];
    const float* Wv = (const float*)d_in[3];
    // d_in[4] = lengths (unused by the reference module)
    float* out = (float*)d_out;

    cudaFuncSetAttribute(qkv_tc, cudaFuncAttributeMaxDynamicSharedMemorySize, QT_SMEM);
    cudaFuncSetAttribute(s_gemm, cudaFuncAttributeMaxDynamicSharedMemorySize, SG_SMEM);
    cudaFuncSetAttribute(pv,     cudaFuncAttributeMaxDynamicSharedMemorySize, PV_SMEM);

    prep_x<<<MTOT * HID / 1024, 256>>>(X);
    prep_w<<<dim3(HID, 3), 256>>>(Wq, Wk, Wv);
    qkv_tc<<<dim3(MTOT / 128, 6), 256, QT_SMEM>>>();
    s_gemm<<<dim3(SEQ / 128, SEQ / 128, BATCH), 256, SG_SMEM>>>();
    pv<<<dim3(SEQ / 64, BATCH), 256, PV_SMEM>>>(out);
}

// round 13
// speedup vs baseline: 6.0653x; 1.0135x over previous
#include <cuda_runtime.h>
#include <cuda_bf16.h>
#include <cuda_fp16.h>
#include <mma.h>
#include <cstdint>
using namespace nvcuda;

#define BATCH 4
#define SEQ   4096
#define HID   256
#define MTOT  (BATCH * SEQ)

__device__ __align__(16) __nv_bfloat16 g_Qh[MTOT * HID];
__device__ __align__(16) __nv_bfloat16 g_Ql[MTOT * HID];
__device__ __align__(16) __nv_bfloat16 g_Kh[MTOT * HID];
__device__ __align__(16) __nv_bfloat16 g_Kl[MTOT * HID];
__device__ __align__(16) __half        g_Vh[MTOT * HID];
__device__ __align__(16) float         g_S [(size_t)BATCH * SEQ * SEQ];   // 256 MB
__device__ __align__(16) __nv_bfloat16 g_Xh[MTOT * HID];
__device__ __align__(16) __nv_bfloat16 g_Xl[MTOT * HID];
__device__ __align__(16) __nv_bfloat16 g_Wth[3 * HID * HID];   // [z][n][k]
__device__ __align__(16) __nv_bfloat16 g_Wtl[3 * HID * HID];
__device__ unsigned g_rmax[MTOT];

__device__ __forceinline__ uint32_t smem_u32(const void* p) {
    uint32_t a;
    asm("{ .reg .u64 t; cvta.to.shared.u64 t, %1; cvt.u32.u64 %0, t; }" : "=r"(a) : "l"(p));
    return a;
}
__device__ __forceinline__ unsigned enc_f(float f) {
    unsigned u = __float_as_uint(f);
    return (u & 0x80000000u) ? ~u : (u | 0x80000000u);
}
__device__ __forceinline__ float dec_f(unsigned e) {
    unsigned u = (e & 0x80000000u) ? (e ^ 0x80000000u) : ~e;
    return __uint_as_float(u);
}
#define CPA(dst, src) \
    asm volatile("cp.async.cg.shared.global [%0], [%1], 16;" :: "r"(dst), "l"(src))
#define CP_COMMIT() asm volatile("cp.async.commit_group;" ::: "memory")
#define CP_WAIT(n)  asm volatile("cp.async.wait_group %0;" :: "n"(n) : "memory")

#define LDSM4(r, a) \
    asm volatile("ldmatrix.sync.aligned.m8n8.x4.shared.b16 {%0,%1,%2,%3}, [%4];" \
        : "=r"((r)[0]), "=r"((r)[1]), "=r"((r)[2]), "=r"((r)[3]) : "r"(a))

__device__ __forceinline__ void mma_bf16(float* c, const uint32_t* a, uint32_t b0, uint32_t b1) {
    asm volatile(
        "mma.sync.aligned.m16n8k16.row.col.f32.bf16.bf16.f32 "
        "{%0,%1,%2,%3}, {%4,%5,%6,%7}, {%8,%9}, {%0,%1,%2,%3};"
        : "+f"(c[0]), "+f"(c[1]), "+f"(c[2]), "+f"(c[3])
        : "r"(a[0]), "r"(a[1]), "r"(a[2]), "r"(a[3]), "r"(b0), "r"(b1));
}

// ---------------------------------------------------------------------------
// prep_x: split X -> bf16 hi/lo; zero g_rmax.
// ---------------------------------------------------------------------------
__global__ __launch_bounds__(256) void prep_x(const float* __restrict__ X)
{
    int idx = blockIdx.x * 256 + threadIdx.x;          // 1 float4 per thread
    float4 v = *reinterpret_cast<const float4*>(X + (size_t)idx * 4);
    __nv_bfloat16 h0 = __float2bfloat16_rn(v.x);
    __nv_bfloat16 h1 = __float2bfloat16_rn(v.y);
    __nv_bfloat16 h2 = __float2bfloat16_rn(v.z);
    __nv_bfloat16 h3 = __float2bfloat16_rn(v.w);
    __nv_bfloat162* H = reinterpret_cast<__nv_bfloat162*>(g_Xh + (size_t)idx * 4);
    __nv_bfloat162* L = reinterpret_cast<__nv_bfloat162*>(g_Xl + (size_t)idx * 4);
    H[0] = {h0, h1}; H[1] = {h2, h3};
    L[0] = {__float2bfloat16_rn(v.x - __bfloat162float(h0)),
            __float2bfloat16_rn(v.y - __bfloat162float(h1))};
    L[1] = {__float2bfloat16_rn(v.z - __bfloat162float(h2)),
            __float2bfloat16_rn(v.w - __bfloat162float(h3))};
    if (idx < MTOT) g_rmax[idx] = 0u;
}

// ---------------------------------------------------------------------------
// prep_w: split + transpose W -> g_Wth/g_Wtl [z][n][k].
// ---------------------------------------------------------------------------
__global__ __launch_bounds__(256) void prep_w(
    const float* __restrict__ Wq, const float* __restrict__ Wk,
    const float* __restrict__ Wv)
{
    const int z = blockIdx.y, k = blockIdx.x, n = threadIdx.x;
    const float* W = (z == 0) ? Wq : (z == 1) ? Wk : Wv;
    float v = W[k * HID + n];
    __nv_bfloat16 h = __float2bfloat16_rn(v);
    g_Wth[(size_t)z * HID * HID + (size_t)n * HID + k] = h;
    g_Wtl[(size_t)z * HID * HID + (size_t)n * HID + k] =
        __float2bfloat16_rn(v - __bfloat162float(h));
}

// ---------------------------------------------------------------------------
// qkv_tc: bf16x3 tensor-core QKV projection.  (1-sync pipeline)
// ---------------------------------------------------------------------------
#define QT_AH    0
#define QT_AL    10240
#define QT_BH    20480
#define QT_BL    30720
#define QT_STG   40960
#define QT_SMEM  81920

__global__ __launch_bounds__(256, 2) void qkv_tc()
{
    extern __shared__ __align__(1024) char smem[];
    const uint32_t sm32 = smem_u32(smem);
    const int tid = threadIdx.x;
    const int w = tid >> 5;
    const int lane = tid & 31;
    const int mw = w >> 1, dw = w & 1;
    const int m0 = blockIdx.x * 128;
    const int z = blockIdx.y >> 1;
    const int n0 = (blockIdx.y & 1) * 128;

    const char* AhG = (const char*)(g_Xh + (size_t)m0 * HID);
    const char* AlG = (const char*)(g_Xl + (size_t)m0 * HID);
    const char* BhG = (const char*)(g_Wth + (size_t)z * HID * HID + (size_t)n0 * HID);
    const char* BlG = (const char*)(g_Wtl + (size_t)z * HID * HID + (size_t)n0 * HID);

    auto loadchunk = [&](int c) {
        uint32_t base = sm32 + (c & 1) * QT_STG;
        #pragma unroll
        for (int e = 0; e < 2; e++) {
            int idx = e * 256 + tid;
            int row = idx >> 2, col = idx & 3;
            uint32_t so = row * 80 + col * 16;
            size_t   go = (size_t)row * 512 + c * 64 + col * 16;
            CPA(base + QT_AH + so, AhG + go);
            CPA(base + QT_AL + so, AlG + go);
            CPA(base + QT_BH + so, BhG + go);
            CPA(base + QT_BL + so, BlG + go);
        }
    };

    float c[2][8][4];
    #pragma unroll
    for (int m = 0; m < 2; m++)
        #pragma unroll
        for (int n = 0; n < 8; n++)
            #pragma unroll
            for (int j = 0; j < 4; j++) c[m][n][j] = 0.0f;

    const uint32_t a_roff = (uint32_t)((lane & 7) + ((lane & 8) ? 8 : 0)) * 80
                          + ((lane & 16) ? 16 : 0);
    const uint32_t b_roff = (uint32_t)((lane & 7) + ((lane & 16) ? 8 : 0)) * 80
                          + ((lane & 8) ? 16 : 0);

    loadchunk(0);
    CP_COMMIT();
    for (int ch = 0; ch < 8; ch++) {
        CP_WAIT(0);
        __syncthreads();
        if (ch + 1 < 8) { loadchunk(ch + 1); CP_COMMIT(); }
        const uint32_t base = sm32 + (ch & 1) * QT_STG;
        #pragma unroll
        for (int kk = 0; kk < 2; kk++) {
            uint32_t ah[2][4], al[2][4];
            #pragma unroll
            for (int m = 0; m < 2; m++) {
                uint32_t arow = (uint32_t)(mw * 32 + m * 16) * 80 + kk * 32;
                LDSM4(ah[m], base + QT_AH + arow + a_roff);
                LDSM4(al[m], base + QT_AL + arow + a_roff);
            }
            uint32_t bh[8][2], bl[8][2];
            #pragma unroll
            for (int nn = 0; nn < 4; nn++) {
                uint32_t brow = (uint32_t)(dw * 64 + nn * 16) * 80 + kk * 32;
                uint32_t r4[4];
                LDSM4(r4, base + QT_BH + brow + b_roff);
                bh[nn * 2][0] = r4[0]; bh[nn * 2][1] = r4[1];
                bh[nn * 2 + 1][0] = r4[2]; bh[nn * 2 + 1][1] = r4[3];
                LDSM4(r4, base + QT_BL + brow + b_roff);
                bl[nn * 2][0] = r4[0]; bl[nn * 2][1] = r4[1];
                bl[nn * 2 + 1][0] = r4[2]; bl[nn * 2 + 1][1] = r4[3];
            }
            #pragma unroll
            for (int m = 0; m < 2; m++)
                #pragma unroll
                for (int n = 0; n < 8; n++) {
                    mma_bf16(c[m][n], ah[m], bh[n][0], bh[n][1]);
                    mma_bf16(c[m][n], ah[m], bl[n][0], bl[n][1]);
                    mma_bf16(c[m][n], al[m], bh[n][0], bh[n][1]);
                }
        }
    }

    const int qr = lane >> 2;
    const int cg = lane & 3;
    const float s = (z == 0) ? 0.0625f : 1.0f;
    #pragma unroll
    for (int m = 0; m < 2; m++) {
        int row0 = m0 + mw * 32 + m * 16 + qr;
        int colb = n0 + dw * 64 + cg * 2;
        if (z == 2) {
            #pragma unroll
            for (int rr = 0; rr < 2; rr++) {
                __half* Vr = g_Vh + (size_t)(row0 + rr * 8) * HID;
                #pragma unroll
                for (int n = 0; n < 8; n++)
                    *reinterpret_cast<__half2*>(Vr + colb + n * 8) =
                        __floats2half2_rn(c[m][n][rr * 2], c[m][n][rr * 2 + 1]);
            }
        } else {
            __nv_bfloat16* Gh = (z == 0) ? g_Qh : g_Kh;
            __nv_bfloat16* Gl = (z == 0) ? g_Ql : g_Kl;
            #pragma unroll
            for (int rr = 0; rr < 2; rr++) {
                size_t rb = (size_t)(row0 + rr * 8) * HID;
                #pragma unroll
                for (int n = 0; n < 8; n++) {
                    float v0 = c[m][n][rr * 2] * s, v1 = c[m][n][rr * 2 + 1] * s;
                    __nv_bfloat16 h0 = __float2bfloat16_rn(v0);
                    __nv_bfloat16 h1 = __float2bfloat16_rn(v1);
                    *reinterpret_cast<__nv_bfloat162*>(Gh + rb + colb + n * 8) = {h0, h1};
                    *reinterpret_cast<__nv_bfloat162*>(Gl + rb + colb + n * 8) =
                        {__float2bfloat16_rn(v0 - __bfloat162float(h0)),
                         __float2bfloat16_rn(v1 - __bfloat162float(h1))};
                }
            }
        }
    }
}

// ---------------------------------------------------------------------------
// Kernel 2: S = Q K^T (bf16 x3) + per-row max.  (1-sync pipeline)
// ---------------------------------------------------------------------------
#define SG_QH    0
#define SG_QL    10240
#define SG_KH    20480
#define SG_KL    30720
#define SG_STG   40960
#define SG_SMEM  81920

__global__ __launch_bounds__(256, 2) void s_gemm()
{
    extern __shared__ __align__(1024) char smem[];
    const uint32_t sm32 = smem_u32(smem);
    const int tid = threadIdx.x;
    const int w = tid >> 5;
    const int lane = tid & 31;
    const int mw = w >> 1, dw = w & 1;
    const int b = blockIdx.z;
    const int q0 = blockIdx.y * 128, k0 = blockIdx.x * 128;

    const char* QhG = (const char*)(g_Qh + (size_t)(b * SEQ + q0) * HID);
    const char* QlG = (const char*)(g_Ql + (size_t)(b * SEQ + q0) * HID);
    const char* KhG = (const char*)(g_Kh + (size_t)(b * SEQ + k0) * HID);
    const char* KlG = (const char*)(g_Kl + (size_t)(b * SEQ + k0) * HID);

    auto loadchunk = [&](int c) {
        uint32_t base = sm32 + (c & 1) * SG_STG;
        #pragma unroll
        for (int e = 0; e < 2; e++) {
            int idx = e * 256 + tid;
            int row = idx >> 2, col = idx & 3;
            uint32_t so = row * 80 + col * 16;
            size_t   go = (size_t)row * 512 + c * 64 + col * 16;
            CPA(base + SG_QH + so, QhG + go);
            CPA(base + SG_QL + so, QlG + go);
            CPA(base + SG_KH + so, KhG + go);
            CPA(base + SG_KL + so, KlG + go);
        }
    };

    float c[2][8][4];
    #pragma unroll
    for (int m = 0; m < 2; m++)
        #pragma unroll
        for (int n = 0; n < 8; n++)
            #pragma unroll
            for (int j = 0; j < 4; j++) c[m][n][j] = 0.0f;

    const uint32_t a_roff = (uint32_t)((lane & 7) + ((lane & 8) ? 8 : 0)) * 80
                          + ((lane & 16) ? 16 : 0);
    const uint32_t b_roff = (uint32_t)((lane & 7) + ((lane & 16) ? 8 : 0)) * 80
                          + ((lane & 8) ? 16 : 0);

    loadchunk(0);
    CP_COMMIT();
    for (int ch = 0; ch < 8; ch++) {
        CP_WAIT(0);
        __syncthreads();
        if (ch + 1 < 8) { loadchunk(ch + 1); CP_COMMIT(); }
        const uint32_t base = sm32 + (ch & 1) * SG_STG;
        #pragma unroll
        for (int kk = 0; kk < 2; kk++) {
            uint32_t ah[2][4], al[2][4];
            #pragma unroll
            for (int m = 0; m < 2; m++) {
                uint32_t arow = (uint32_t)(mw * 32 + m * 16) * 80 + kk * 32;
                LDSM4(ah[m], base + SG_QH + arow + a_roff);
                LDSM4(al[m], base + SG_QL + arow + a_roff);
            }
            uint32_t bh[8][2], bl[8][2];
            #pragma unroll
            for (int nn = 0; nn < 4; nn++) {
                uint32_t brow = (uint32_t)(dw * 64 + nn * 16) * 80 + kk * 32;
                uint32_t r4[4];
                LDSM4(r4, base + SG_KH + brow + b_roff);
                bh[nn * 2][0] = r4[0]; bh[nn * 2][1] = r4[1];
                bh[nn * 2 + 1][0] = r4[2]; bh[nn * 2 + 1][1] = r4[3];
                LDSM4(r4, base + SG_KL + brow + b_roff);
                bl[nn * 2][0] = r4[0]; bl[nn * 2][1] = r4[1];
                bl[nn * 2 + 1][0] = r4[2]; bl[nn * 2 + 1][1] = r4[3];
            }
            #pragma unroll
            for (int m = 0; m < 2; m++)
                #pragma unroll
                for (int n = 0; n < 8; n++) {
                    mma_bf16(c[m][n], ah[m], bh[n][0], bh[n][1]);
                    mma_bf16(c[m][n], ah[m], bl[n][0], bl[n][1]);
                    mma_bf16(c[m][n], al[m], bh[n][0], bh[n][1]);
                }
        }
    }

    const int qr = lane >> 2;
    const int cg = lane & 3;
    #pragma unroll
    for (int m = 0; m < 2; m++) {
        float mx0 = c[m][0][0], mx1 = c[m][0][2];
        #pragma unroll
        for (int n = 0; n < 8; n++) {
            mx0 = fmaxf(mx0, fmaxf(c[m][n][0], c[m][n][1]));
            mx1 = fmaxf(mx1, fmaxf(c[m][n][2], c[m][n][3]));
        }
        mx0 = fmaxf(mx0, __shfl_xor_sync(0xFFFFFFFF, mx0, 1));
        mx0 = fmaxf(mx0, __shfl_xor_sync(0xFFFFFFFF, mx0, 2));
        mx1 = fmaxf(mx1, __shfl_xor_sync(0xFFFFFFFF, mx1, 1));
        mx1 = fmaxf(mx1, __shfl_xor_sync(0xFFFFFFFF, mx1, 2));
        if (cg == 0) {
            atomicMax(&g_rmax[b * SEQ + q0 + mw * 32 + m * 16 + qr], enc_f(mx0));
            atomicMax(&g_rmax[b * SEQ + q0 + mw * 32 + m * 16 + qr + 8], enc_f(mx1));
        }
        float* r0 = g_S + ((size_t)b * SEQ + q0 + mw * 32 + m * 16 + qr) * SEQ + k0 + dw * 64;
        float* r1 = r0 + (size_t)8 * SEQ;
        #pragma unroll
        for (int n = 0; n < 8; n++) {
            *reinterpret_cast<float2*>(r0 + n * 8 + cg * 2) = make_float2(c[m][n][0], c[m][n][1]);
            *reinterpret_cast<float2*>(r1 + n * 8 + cg * 2) = make_float2(c[m][n][2], c[m][n][3]);
        }
    }
}

// ---------------------------------------------------------------------------
// Kernel 3: O = softmax(S) V, fp16 HMMA.  128 q rows/CTA, 512 thr, KT=64.
// grid (32, 4).  Warps: 4 m-warps x 4 n-warps, 32x64 each.  2 syncs/iter.
// ---------------------------------------------------------------------------
#define PV_S0   0
#define PV_S1   34816                 // S: 128 x 272 B
#define PV_V0   69632                 // V: 64 x 528 B
#define PV_V1   103424
#define PV_P    137216                // P: 128 x 144 B (ld 72 halves)
#define PV_PLD  72
#define PV_VLD  264
#define PV_MS   155648                // 128 f32
#define PV_RL   156160                // 128 x 4 f32
#define PV_SMEM 158720
#define PV_OLD  264                   // O staging ld (f32), at offset 0
#define PV_NT   (SEQ / 64)

__global__ __launch_bounds__(512, 1) void pv(float* __restrict__ out)
{
    extern __shared__ __align__(1024) char smem[];
    const uint32_t sm32 = smem_u32(smem);
    const int tid = threadIdx.x;
    const int w = tid >> 5;
    const int mw2 = w >> 2, dv = w & 3;
    const int r = tid >> 2, g = tid & 3;       // softmax: row 0..127, col group
    const int b = blockIdx.y;
    const int q0 = blockIdx.x * 128;

    const char* SG = (const char*)(g_S + ((size_t)b * SEQ + q0) * SEQ);
    const char* VG = (const char*)(g_Vh + (size_t)b * SEQ * HID);
    float* ms = (float*)(smem + PV_MS);
    float* Rl = (float*)(smem + PV_RL);

    if (tid < 128) ms[tid] = dec_f(g_rmax[b * SEQ + q0 + tid]);

    auto loadtile = [&](int kt) {
        uint32_t sb = sm32 + ((kt & 1) ? PV_S1 : PV_S0);
        uint32_t vb = sm32 + ((kt & 1) ? PV_V1 : PV_V0);
        #pragma unroll
        for (int e = 0; e < 4; e++) {          // S: 128 rows x 256 B
            int idx = e * 512 + tid, row = idx >> 4, col = idx & 15;
            CPA(sb + row * 272 + col * 16,
                SG + (size_t)row * (SEQ * 4) + (size_t)kt * 256 + col * 16);
        }
        #pragma unroll
        for (int e = 0; e < 4; e++) {          // V: 64 rows x 512 B (fp16)
            int idx = e * 512 + tid, row = idx >> 5, col = idx & 31;
            CPA(vb + row * 528 + col * 16,
                VG + (size_t)(kt * 64 + row) * 512 + col * 16);
        }
    };

    wmma::fragment<wmma::accumulator, 16, 16, 16, float> accO[2][4];
    #pragma unroll
    for (int m = 0; m < 2; m++)
        #pragma unroll
        for (int n = 0; n < 4; n++) wmma::fill_fragment(accO[m][n], 0.0f);
    float lpart = 0.0f;
    const float L2E = 1.44269504f;

    loadtile(0);
    CP_COMMIT();
    __syncthreads();                  // ms[] visible
    const float mr = ms[r];
    for (int kt = 0; kt < PV_NT; kt++) {
        CP_WAIT(0);
        __syncthreads();              // tile kt visible; prev-iter reads done
        if (kt + 1 < PV_NT) { loadtile(kt + 1); CP_COMMIT(); }
        const char* Sb = smem + ((kt & 1) ? PV_S1 : PV_S0);
        const __half* Vs = (const __half*)(smem + ((kt & 1) ? PV_V1 : PV_V0));

        {   // softmax strip: row r, 16 cols at g*16; P fp16, l from rounded p
            const float4* srow = (const float4*)(Sb + r * 272 + g * 64);
            __half2* prow = (__half2*)(smem + PV_P + r * 144 + g * 32);
            #pragma unroll
            for (int j4 = 0; j4 < 4; j4++) {
                float4 s4 = srow[j4];
                float p0 = exp2f((s4.x - mr) * L2E);
                float p1 = exp2f((s4.y - mr) * L2E);
                float p2 = exp2f((s4.z - mr) * L2E);
                float p3 = exp2f((s4.w - mr) * L2E);
                __half2 h01 = __floats2half2_rn(p0, p1);
                __half2 h23 = __floats2half2_rn(p2, p3);
                float2 b01 = __half22float2(h01);
                float2 b23 = __half22float2(h23);
                lpart += (b01.x + b01.y) + (b23.x + b23.y);
                prow[j4 * 2 + 0] = h01;
                prow[j4 * 2 + 1] = h23;
            }
        }
        __syncthreads();              // P visible to MMA warps

        {   // PV accumulate (fp16 x fp16 -> fp32)
            const __half* Ps = (const __half*)(smem + PV_P);
            wmma::fragment<wmma::matrix_a, 16, 16, 16, __half, wmma::row_major> pa[2];
            wmma::fragment<wmma::matrix_b, 16, 16, 16, __half, wmma::row_major> vb;
            #pragma unroll
            for (int kk = 0; kk < 4; kk++) {
                #pragma unroll
                for (int m = 0; m < 2; m++)
                    wmma::load_matrix_sync(pa[m], Ps + (mw2 * 32 + m * 16) * PV_PLD + kk * 16, PV_PLD);
                #pragma unroll
                for (int n = 0; n < 4; n++) {
                    wmma::load_matrix_sync(vb, Vs + (kk * 16) * PV_VLD + dv * 64 + n * 16, PV_VLD);
                    #pragma unroll
                    for (int m = 0; m < 2; m++)
                        wmma::mma_sync(accO[m][n], pa[m], vb, accO[m][n]);
                }
            }
        }
    }

    // epilogue: stage O via smem (reuses S/V buffers), scale by 1/l, write out
    Rl[r * 4 + g] = lpart;
    __syncthreads();
    float* Os = (float*)smem;         // 128 x 264 f32 = 135168 B < PV_P
    #pragma unroll
    for (int m = 0; m < 2; m++)
        #pragma unroll
        for (int n = 0; n < 4; n++)
            wmma::store_matrix_sync(Os + (mw2 * 32 + m * 16) * PV_OLD + dv * 64 + n * 16,
                                    accO[m][n], PV_OLD, wmma::mem_row_major);
    __syncthreads();
    const float linv = 1.0f / (Rl[r * 4 + 0] + Rl[r * 4 + 1] + Rl[r * 4 + 2] + Rl[r * 4 + 3]);
    float* orow = out + ((size_t)b * SEQ + q0 + r) * HID + g * 64;
    const float* srow = Os + r * PV_OLD + g * 64;
    #pragma unroll
    for (int j = 0; j < 16; j++) {
        float4 v = *reinterpret_cast<const float4*>(srow + j * 4);
        v.x *= linv; v.y *= linv; v.z *= linv; v.w *= linv;
        *reinterpret_cast<float4*>(orow + j * 4) = v;
    }
}

// ---------------------------------------------------------------------------
extern "C" void kernel_launch(void* const* d_in, const int* in_sizes, int n_in,
                              void* d_out, int out_size)
{
    const float* X  = (const float*)d_in[0];
    const float* Wq = (const float*)d_in[1];
    const float* Wk = (const float*)d_in[2];
    const float* Wv = (const float*)d_in[3];
    // d_in[4] = lengths (unused by the reference module)
    float* out = (float*)d_out;

    cudaFuncSetAttribute(qkv_tc, cudaFuncAttributeMaxDynamicSharedMemorySize, QT_SMEM);
    cudaFuncSetAttribute(s_gemm, cudaFuncAttributeMaxDynamicSharedMemorySize, SG_SMEM);
    cudaFuncSetAttribute(pv,     cudaFuncAttributeMaxDynamicSharedMemorySize, PV_SMEM);

    prep_x<<<MTOT * HID / 1024, 256>>>(X);
    prep_w<<<dim3(HID, 3), 256>>>(Wq, Wk, Wv);
    qkv_tc<<<dim3(MTOT / 128, 6), 256, QT_SMEM>>>();
    s_gemm<<<dim3(SEQ / 128, SEQ / 128, BATCH), 256, SG_SMEM>>>();
    pv<<<dim3(SEQ / 128, BATCH), 512, PV_SMEM>>>(out);
}